// round 8
// baseline (speedup 1.0000x reference)
#include <cuda_runtime.h>
#include <cuda_fp16.h>
#include <math.h>
#include <stdint.h>

// Problem constants
#define B_  4
#define T_  2048
#define C_  1024
#define NH_ 16
#define HD_ 64
#define BH_ (B_*NH_)     // 64
#define M_  (B_*T_)      // 8192

// Scratch (allocation-free device globals), fp16 hi/lo split scheme.
// B-side operands only ever need the hi part (2-MMA split: Ah*Bh + Al*Bh).
__device__ __half g_xh[M_*C_],      g_xl[M_*C_];        // x split
__device__ __half g_wqkvh[C_*3*C_];                     // Wqkv hi [K][N]
__device__ __half g_wph[C_*C_];                         // Wproj hi [K][N]
__device__ __half g_qh[BH_*T_*HD_], g_ql[BH_*T_*HD_];   // Q hi/lo  [B,NH,T,HD]
__device__ __half g_kh[BH_*T_*HD_];                     // K hi only
__device__ __half g_vh[BH_*T_*HD_];                     // V hi only
__device__ __half g_yh[M_*C_],      g_yl[M_*C_];        // attention out split

__device__ __forceinline__ uint32_t smem_u32(const void* p) {
    return (uint32_t)__cvta_generic_to_shared(p);
}

#define LDSM4(R, ptr)                                                          \
    asm volatile("ldmatrix.sync.aligned.m8n8.x4.shared.b16 {%0,%1,%2,%3}, [%4];" \
                 : "=r"((R)[0]), "=r"((R)[1]), "=r"((R)[2]), "=r"((R)[3])      \
                 : "r"(smem_u32(ptr)))

#define LDSM4T(R, ptr)                                                         \
    asm volatile("ldmatrix.sync.aligned.m8n8.x4.trans.shared.b16 {%0,%1,%2,%3}, [%4];" \
                 : "=r"((R)[0]), "=r"((R)[1]), "=r"((R)[2]), "=r"((R)[3])      \
                 : "r"(smem_u32(ptr)))

#define MMA16816(D, A, b0, b1)                                                 \
    asm volatile("mma.sync.aligned.m16n8k16.row.col.f32.f16.f16.f32 "          \
                 "{%0,%1,%2,%3}, {%4,%5,%6,%7}, {%8,%9}, {%0,%1,%2,%3};"       \
                 : "+f"((D)[0]), "+f"((D)[1]), "+f"((D)[2]), "+f"((D)[3])      \
                 : "r"((A)[0]), "r"((A)[1]), "r"((A)[2]), "r"((A)[3]),         \
                   "r"(b0), "r"(b1))

__device__ __forceinline__ void cp16(uint32_t dst, const void* src) {
    asm volatile("cp.async.cg.shared.global [%0], [%1], 16;" :: "r"(dst), "l"(src));
}
#define CP_COMMIT() asm volatile("cp.async.commit_group;")
#define CP_WAIT0()  asm volatile("cp.async.wait_group 0;")

__device__ __forceinline__ void split_fp16(float x, __half& h, __half& l) {
    h = __float2half_rn(x);
    l = __float2half_rn(x - __half2float(h));
}

__device__ __forceinline__ uint32_t pack2h(float a, float b) {
    __half2 t = __halves2half2(__float2half_rn(a), __float2half_rn(b));
    return *reinterpret_cast<uint32_t*>(&t);
}

// ---------------------------------------------------------------------------
// Elementwise fp32 -> fp16 hi/lo split
// ---------------------------------------------------------------------------
__global__ __launch_bounds__(256) void split_pass(
    const float* __restrict__ in, __half* __restrict__ oh,
    __half* __restrict__ ol, int n4)
{
    int i = blockIdx.x * blockDim.x + threadIdx.x;
    if (i >= n4) return;
    float4 v = reinterpret_cast<const float4*>(in)[i];
    __half h0, l0, h1, l1, h2, l2, h3, l3;
    split_fp16(v.x, h0, l0); split_fp16(v.y, h1, l1);
    split_fp16(v.z, h2, l2); split_fp16(v.w, h3, l3);
    reinterpret_cast<__half2*>(oh)[2*i]   = __halves2half2(h0, h1);
    reinterpret_cast<__half2*>(oh)[2*i+1] = __halves2half2(h2, h3);
    reinterpret_cast<__half2*>(ol)[2*i]   = __halves2half2(l0, l1);
    reinterpret_cast<__half2*>(ol)[2*i+1] = __halves2half2(l2, l3);
}

// fp32 -> fp16 hi only
__global__ __launch_bounds__(256) void conv_pass(
    const float* __restrict__ in, __half* __restrict__ oh, int n4)
{
    int i = blockIdx.x * blockDim.x + threadIdx.x;
    if (i >= n4) return;
    float4 v = reinterpret_cast<const float4*>(in)[i];
    reinterpret_cast<__half2*>(oh)[2*i]   = __halves2half2(__float2half_rn(v.x), __float2half_rn(v.y));
    reinterpret_cast<__half2*>(oh)[2*i+1] = __halves2half2(__float2half_rn(v.z), __float2half_rn(v.w));
}

// ---------------------------------------------------------------------------
// GEMM, fp16 2-MMA split: C = Ah*Bh + Al*Bh (+bias). cp.async 2-stage.
// Block 128x128, BK=32, 256 threads = 8 warps (2m x 4n), warp tile 64x32.
// MODE 0: A = g_x{h,l}, B = g_wqkvh; scatter q(hi,lo), k(hi), v(hi).
// MODE 1: A = g_y{h,l}, B = g_wph;  fp32 row-major output + bias.
// ---------------------------------------------------------------------------
template <int MODE>
__global__ __launch_bounds__(256, 2) void gemm_pre(
    const float* __restrict__ bias, float* __restrict__ Cout, int M, int N, int K)
{
    constexpr int LDA = 40;    // A smem stride (32+8), fp16
    constexpr int LDB = 136;   // B smem stride (128+8), fp16
    constexpr int ASZ = 128 * LDA;
    constexpr int BSZ = 32 * LDB;
    constexpr int STAGE = 2 * ASZ + BSZ;     // Ah, Al, Bh

    extern __shared__ __half smem[];

    const __half* Agh = (MODE == 0) ? g_xh : g_yh;
    const __half* Agl = (MODE == 0) ? g_xl : g_yl;
    const __half* Wgh = (MODE == 0) ? g_wqkvh : g_wph;

    int tid  = threadIdx.x;
    int lane = tid & 31, warp = tid >> 5;
    int cRow = blockIdx.y, cCol = blockIdx.x;
    int warpM = warp & 1, warpN = warp >> 1;      // 2m x 4n
    int mr0 = warpM * 64;
    int n0w = warpN * 32;

    const __half* Abh = Agh + (size_t)cRow * 128 * K;
    const __half* Abl = Agl + (size_t)cRow * 128 * K;
    const __half* Wbh = Wgh + cCol * 128;

    int ar0 = tid >> 2,  aq0 = (tid & 3) << 3;
    int ar1 = ar0 + 64;
    int br0 = tid >> 4,  bq0 = (tid & 15) << 3;
    int br1 = br0 + 16;

    uint32_t smem_base = smem_u32(smem);

    auto issue_stage = [&](int st, int k0) {
        uint32_t sb = smem_base + st * STAGE * 2;
        uint32_t ah = sb, al = sb + ASZ * 2, bh = sb + 2 * ASZ * 2;
        cp16(ah + (ar0 * LDA + aq0) * 2, Abh + (size_t)ar0 * K + k0 + aq0);
        cp16(ah + (ar1 * LDA + aq0) * 2, Abh + (size_t)ar1 * K + k0 + aq0);
        cp16(al + (ar0 * LDA + aq0) * 2, Abl + (size_t)ar0 * K + k0 + aq0);
        cp16(al + (ar1 * LDA + aq0) * 2, Abl + (size_t)ar1 * K + k0 + aq0);
        cp16(bh + (br0 * LDB + bq0) * 2, Wbh + (size_t)(k0 + br0) * N + bq0);
        cp16(bh + (br1 * LDB + bq0) * 2, Wbh + (size_t)(k0 + br1) * N + bq0);
    };

    float acc[4][4][4];   // [mi][nj][frag]
    #pragma unroll
    for (int i = 0; i < 4; i++)
        #pragma unroll
        for (int j = 0; j < 4; j++)
            #pragma unroll
            for (int q = 0; q < 4; q++) acc[i][j][q] = 0.f;

    issue_stage(0, 0);
    CP_COMMIT();

    int NT = K / 32;
    for (int it = 0; it < NT; it++) {
        CP_WAIT0();
        __syncthreads();
        if (it + 1 < NT) {
            issue_stage((it + 1) & 1, (it + 1) * 32);
            CP_COMMIT();
        }

        __half* Ah = smem + (it & 1) * STAGE;
        __half* Al = Ah + ASZ;
        __half* Bh = Al + ASZ;

        #pragma unroll
        for (int k16 = 0; k16 < 2; k16++) {
            int kk = k16 * 16;
            uint32_t ahf[4][4], alf[4][4], bhf[2][4];

            #pragma unroll
            for (int mi = 0; mi < 4; mi++) {
                int off = (mr0 + mi * 16 + (lane & 15)) * LDA + kk + ((lane >> 4) << 3);
                LDSM4(ahf[mi], &Ah[off]);
                LDSM4(alf[mi], &Al[off]);
            }
            #pragma unroll
            for (int g = 0; g < 2; g++) {
                int r = kk + ((lane & 16) >> 1) + (lane & 7);
                int c = n0w + g * 16 + (lane & 8);
                LDSM4T(bhf[g], &Bh[r * LDB + c]);
            }

            #pragma unroll
            for (int mi = 0; mi < 4; mi++)
                #pragma unroll
                for (int nj = 0; nj < 4; nj++) {
                    int g = nj >> 1, h = nj & 1;
                    MMA16816(acc[mi][nj], ahf[mi],
                             h ? bhf[g][1] : bhf[g][0], h ? bhf[g][3] : bhf[g][2]);
                }
            #pragma unroll
            for (int mi = 0; mi < 4; mi++)
                #pragma unroll
                for (int nj = 0; nj < 4; nj++) {
                    int g = nj >> 1, h = nj & 1;
                    MMA16816(acc[mi][nj], alf[mi],
                             h ? bhf[g][1] : bhf[g][0], h ? bhf[g][3] : bhf[g][2]);
                }
        }
        __syncthreads();
    }

    // --- epilogue ---
    int rbase = cRow * 128 + mr0 + (lane >> 2);
    int cbase = cCol * 128 + n0w + ((lane & 3) << 1);

    #pragma unroll
    for (int mi = 0; mi < 4; mi++) {
        #pragma unroll
        for (int nj = 0; nj < 4; nj++) {
            int m0 = rbase + mi * 16;
            int n  = cbase + nj * 8;
            float bv0 = bias[n], bv1 = bias[n + 1];
            float v00 = acc[mi][nj][0] + bv0, v01 = acc[mi][nj][1] + bv1;
            float v10 = acc[mi][nj][2] + bv0, v11 = acc[mi][nj][3] + bv1;
            if (MODE == 1) {
                *reinterpret_cast<float2*>(&Cout[(size_t)m0 * N + n])       = make_float2(v00, v01);
                *reinterpret_cast<float2*>(&Cout[(size_t)(m0 + 8) * N + n]) = make_float2(v10, v11);
            } else {
                int which = n / C_;
                int c = n - which * C_;
                int h = c >> 6, d = c & 63;
                int b0i = m0 >> 11, t0 = m0 & 2047;
                int b1i = (m0 + 8) >> 11, t1 = (m0 + 8) & 2047;
                size_t i0 = (((size_t)b0i * NH_ + h) * T_ + t0) * HD_ + d;
                size_t i1 = (((size_t)b1i * NH_ + h) * T_ + t1) * HD_ + d;
                if (which == 0) {
                    __half h00, l00, h01, l01, h10, l10, h11, l11;
                    split_fp16(v00, h00, l00); split_fp16(v01, h01, l01);
                    split_fp16(v10, h10, l10); split_fp16(v11, h11, l11);
                    *reinterpret_cast<__half2*>(&g_qh[i0]) = __halves2half2(h00, h01);
                    *reinterpret_cast<__half2*>(&g_ql[i0]) = __halves2half2(l00, l01);
                    *reinterpret_cast<__half2*>(&g_qh[i1]) = __halves2half2(h10, h11);
                    *reinterpret_cast<__half2*>(&g_ql[i1]) = __halves2half2(l10, l11);
                } else {
                    __half* dh = (which == 1) ? g_kh : g_vh;
                    *reinterpret_cast<__half2*>(&dh[i0]) =
                        __halves2half2(__float2half_rn(v00), __float2half_rn(v01));
                    *reinterpret_cast<__half2*>(&dh[i1]) =
                        __halves2half2(__float2half_rn(v10), __float2half_rn(v11));
                }
            }
        }
    }
}

// ---------------------------------------------------------------------------
// Flash attention, fp16 2-MMA split, causal. CTA: 128 q-rows, 64-key iters.
// S = Qh*Kh + Ql*Kh (K hi only). O += Ph*Vh + Pl*Vh (V hi only).
// ---------------------------------------------------------------------------
__global__ __launch_bounds__(256) void flash_mma_kernel()
{
    constexpr int LDS_ = 72;
    extern __shared__ __half smf[];
    __half* Qh = smf;                 // [128][72]
    __half* Ql = Qh + 128 * LDS_;
    __half* Kh = Ql + 128 * LDS_;     // [64][72]
    __half* Vh = Kh + 64 * LDS_;      // [64][72]

    int bh = blockIdx.y;
    int qt = gridDim.x - 1 - blockIdx.x;
    int q0 = qt * 128;
    int tid = threadIdx.x;
    int warp = tid >> 5, lane = tid & 31;
    int wrow = warp * 16;
    int g = lane >> 2, t2 = (lane & 3) << 1;

    const __half* Qgh = g_qh + ((size_t)bh * T_ + q0) * HD_;
    const __half* Qgl = g_ql + ((size_t)bh * T_ + q0) * HD_;

    #pragma unroll
    for (int i = 0; i < 4; i++) {
        int idx = (tid + i * 256) * 8;
        int r = idx >> 6, c = idx & 63;
        *reinterpret_cast<uint4*>(&Qh[r * LDS_ + c]) =
            *reinterpret_cast<const uint4*>(&Qgh[r * 64 + c]);
        *reinterpret_cast<uint4*>(&Ql[r * LDS_ + c]) =
            *reinterpret_cast<const uint4*>(&Qgl[r * 64 + c]);
    }

    float O[8][4];
    #pragma unroll
    for (int i = 0; i < 8; i++)
        #pragma unroll
        for (int q = 0; q < 4; q++) O[i][q] = 0.f;
    float m0 = -INFINITY, m1 = -INFINITY, l0 = 0.f, l1 = 0.f;

    const float scale = 0.125f;
    int row0 = q0 + wrow + g;
    int row1 = row0 + 8;

    __syncthreads();

    int kt_max = 2 * qt + 1;
    for (int kt = 0; kt <= kt_max; kt++) {
        int k0 = kt * 64;

        {
            const __half* kgh = g_kh + ((size_t)bh * T_ + k0) * HD_;
            const __half* vgh = g_vh + ((size_t)bh * T_ + k0) * HD_;
            #pragma unroll
            for (int i = 0; i < 2; i++) {
                int idx = (tid + i * 256) * 8;
                int r = idx >> 6, c = idx & 63;
                *reinterpret_cast<uint4*>(&Kh[r * LDS_ + c]) = *reinterpret_cast<const uint4*>(&kgh[r * 64 + c]);
                *reinterpret_cast<uint4*>(&Vh[r * LDS_ + c]) = *reinterpret_cast<const uint4*>(&vgh[r * 64 + c]);
            }
        }
        __syncthreads();

        float S[8][4];
        #pragma unroll
        for (int j = 0; j < 8; j++)
            #pragma unroll
            for (int q = 0; q < 4; q++) S[j][q] = 0.f;

        #pragma unroll
        for (int ks = 0; ks < 4; ks++) {
            int kk = ks * 16;
            uint32_t qhf[4], qlf[4];
            {
                int off = (wrow + (lane & 15)) * LDS_ + kk + ((lane >> 4) << 3);
                LDSM4(qhf, &Qh[off]);
                LDSM4(qlf, &Ql[off]);
            }
            uint32_t bKh[8][2];
            #pragma unroll
            for (int tp = 0; tp < 4; tp++) {
                uint32_t R[4];
                int off = (tp * 16 + (lane & 7) + ((lane >> 4) << 3)) * LDS_
                          + kk + (((lane >> 3) & 1) << 3);
                LDSM4(R, &Kh[off]);
                bKh[2*tp][0] = R[0]; bKh[2*tp][1] = R[1];
                bKh[2*tp+1][0] = R[2]; bKh[2*tp+1][1] = R[3];
            }
            #pragma unroll
            for (int j = 0; j < 8; j++)
                MMA16816(S[j], qhf, bKh[j][0], bKh[j][1]);
            #pragma unroll
            for (int j = 0; j < 8; j++)
                MMA16816(S[j], qlf, bKh[j][0], bKh[j][1]);
        }

        if (kt >= 2 * qt) {
            #pragma unroll
            for (int j = 0; j < 8; j++) {
                int key = k0 + j * 8 + t2;
                if (key     > row0) S[j][0] = -1e30f;
                if (key + 1 > row0) S[j][1] = -1e30f;
                if (key     > row1) S[j][2] = -1e30f;
                if (key + 1 > row1) S[j][3] = -1e30f;
            }
        }

        float mx0 = -1e30f, mx1 = -1e30f;
        #pragma unroll
        for (int j = 0; j < 8; j++) {
            mx0 = fmaxf(mx0, fmaxf(S[j][0], S[j][1]));
            mx1 = fmaxf(mx1, fmaxf(S[j][2], S[j][3]));
        }
        #pragma unroll
        for (int off = 1; off <= 2; off <<= 1) {
            mx0 = fmaxf(mx0, __shfl_xor_sync(0xffffffffu, mx0, off));
            mx1 = fmaxf(mx1, __shfl_xor_sync(0xffffffffu, mx1, off));
        }
        float mn0 = fmaxf(m0, mx0 * scale);
        float mn1 = fmaxf(m1, mx1 * scale);
        float a0 = __expf(m0 - mn0);
        float a1 = __expf(m1 - mn1);
        m0 = mn0; m1 = mn1;

        float s0 = 0.f, s1 = 0.f;
        #pragma unroll
        for (int j = 0; j < 8; j++) {
            S[j][0] = __expf(fmaf(S[j][0], scale, -mn0));
            S[j][1] = __expf(fmaf(S[j][1], scale, -mn0));
            S[j][2] = __expf(fmaf(S[j][2], scale, -mn1));
            S[j][3] = __expf(fmaf(S[j][3], scale, -mn1));
            s0 += S[j][0] + S[j][1];
            s1 += S[j][2] + S[j][3];
        }
        #pragma unroll
        for (int off = 1; off <= 2; off <<= 1) {
            s0 += __shfl_xor_sync(0xffffffffu, s0, off);
            s1 += __shfl_xor_sync(0xffffffffu, s1, off);
        }
        l0 = l0 * a0 + s0;
        l1 = l1 * a1 + s1;
        #pragma unroll
        for (int i = 0; i < 8; i++) {
            O[i][0] *= a0; O[i][1] *= a0;
            O[i][2] *= a1; O[i][3] *= a1;
        }

        // ---- O += P V (fp16 2-MMA) ----
        #pragma unroll
        for (int ks = 0; ks < 4; ks++) {
            int j0 = 2 * ks, j1 = 2 * ks + 1;
            uint32_t aPh[4], aPl[4];
            aPh[0] = pack2h(S[j0][0], S[j0][1]);
            aPh[1] = pack2h(S[j0][2], S[j0][3]);
            aPh[2] = pack2h(S[j1][0], S[j1][1]);
            aPh[3] = pack2h(S[j1][2], S[j1][3]);
            {
                __half2 h;
                h = *reinterpret_cast<__half2*>(&aPh[0]);
                aPl[0] = pack2h(S[j0][0] - __low2float(h), S[j0][1] - __high2float(h));
                h = *reinterpret_cast<__half2*>(&aPh[1]);
                aPl[1] = pack2h(S[j0][2] - __low2float(h), S[j0][3] - __high2float(h));
                h = *reinterpret_cast<__half2*>(&aPh[2]);
                aPl[2] = pack2h(S[j1][0] - __low2float(h), S[j1][1] - __high2float(h));
                h = *reinterpret_cast<__half2*>(&aPh[3]);
                aPl[3] = pack2h(S[j1][2] - __low2float(h), S[j1][3] - __high2float(h));
            }
            uint32_t Rh[4][4];
            #pragma unroll
            for (int gd = 0; gd < 4; gd++) {
                int off = (ks * 16 + ((lane & 16) >> 1) + (lane & 7)) * LDS_
                          + gd * 16 + (lane & 8);
                LDSM4T(Rh[gd], &Vh[off]);
            }
            #pragma unroll
            for (int gd = 0; gd < 4; gd++) {
                MMA16816(O[gd*2+0], aPh, Rh[gd][0], Rh[gd][2]);
                MMA16816(O[gd*2+1], aPh, Rh[gd][1], Rh[gd][3]);
            }
            #pragma unroll
            for (int gd = 0; gd < 4; gd++) {
                MMA16816(O[gd*2+0], aPl, Rh[gd][0], Rh[gd][2]);
                MMA16816(O[gd*2+1], aPl, Rh[gd][1], Rh[gd][3]);
            }
        }
        __syncthreads();
    }

    int b = bh >> 4, h = bh & 15;
    float inv0 = 1.f / l0, inv1 = 1.f / l1;
    size_t base0 = ((size_t)b * T_ + row0) * C_ + h * 64 + t2;
    size_t base1 = ((size_t)b * T_ + row1) * C_ + h * 64 + t2;
    #pragma unroll
    for (int i = 0; i < 8; i++) {
        float v0 = O[i][0] * inv0, v1 = O[i][1] * inv0;
        float v2 = O[i][2] * inv1, v3 = O[i][3] * inv1;
        __half h0, l0b, h1, l1b, h2, l2b, h3, l3b;
        split_fp16(v0, h0, l0b); split_fp16(v1, h1, l1b);
        split_fp16(v2, h2, l2b); split_fp16(v3, h3, l3b);
        *reinterpret_cast<__half2*>(&g_yh[base0 + i * 8]) = __halves2half2(h0, h1);
        *reinterpret_cast<__half2*>(&g_yl[base0 + i * 8]) = __halves2half2(l0b, l1b);
        *reinterpret_cast<__half2*>(&g_yh[base1 + i * 8]) = __halves2half2(h2, h3);
        *reinterpret_cast<__half2*>(&g_yl[base1 + i * 8]) = __halves2half2(l2b, l3b);
    }
}

// ---------------------------------------------------------------------------
extern "C" void kernel_launch(void* const* d_in, const int* in_sizes, int n_in,
                              void* d_out, int out_size)
{
    const float* x     = (const float*)d_in[0];
    const float* Wqkv  = (const float*)d_in[1];
    const float* bqkv  = (const float*)d_in[2];
    const float* Wproj = (const float*)d_in[3];
    const float* bproj = (const float*)d_in[4];
    float* out = (float*)d_out;

    static __half *xh_p = nullptr, *xl_p, *wqh_p, *wph_p;
    if (!xh_p) {
        cudaGetSymbolAddress((void**)&xh_p,  g_xh);
        cudaGetSymbolAddress((void**)&xl_p,  g_xl);
        cudaGetSymbolAddress((void**)&wqh_p, g_wqkvh);
        cudaGetSymbolAddress((void**)&wph_p, g_wph);
    }

    // 0) Pre-split x (hi/lo); convert weights (hi only)
    split_pass<<<(M_ * C_ / 4 + 255) / 256, 256>>>(x, xh_p, xl_p, M_ * C_ / 4);
    conv_pass<<<(C_ * 3 * C_ / 4 + 255) / 256, 256>>>(Wqkv, wqh_p, C_ * 3 * C_ / 4);
    conv_pass<<<(C_ * C_ / 4 + 255) / 256, 256>>>(Wproj, wph_p, C_ * C_ / 4);

    const int gemm_smem = 2 * (2 * 128 * 40 + 32 * 136) * (int)sizeof(__half); // 58368

    // 1) QKV GEMM -> q(hi,lo), k(hi), v(hi)
    {
        cudaFuncSetAttribute(gemm_pre<0>, cudaFuncAttributeMaxDynamicSharedMemorySize, gemm_smem);
        dim3 grid(3072 / 128, 8192 / 128);
        gemm_pre<0><<<grid, 256, gemm_smem>>>(bqkv, nullptr, M_, 3 * C_, C_);
    }

    // 2) Flash attention, writes g_yh/g_yl
    {
        const int smem = (2 * 128 * 72 + 2 * 64 * 72) * (int)sizeof(__half); // 55296
        cudaFuncSetAttribute(flash_mma_kernel, cudaFuncAttributeMaxDynamicSharedMemorySize, smem);
        flash_mma_kernel<<<dim3(16, 64), 256, smem>>>();
    }

    // 3) Projection GEMM: y @ Wproj + bproj -> out
    {
        cudaFuncSetAttribute(gemm_pre<1>, cudaFuncAttributeMaxDynamicSharedMemorySize, gemm_smem);
        dim3 grid(1024 / 128, 8192 / 128);
        gemm_pre<1><<<grid, 256, gemm_smem>>>(bproj, out, M_, C_, C_);
    }
}

// round 9
// speedup vs baseline: 1.1032x; 1.1032x over previous
#include <cuda_runtime.h>
#include <cuda_bf16.h>
#include <math.h>
#include <stdint.h>

// Problem constants
#define B_  4
#define T_  2048
#define C_  1024
#define NH_ 16
#define HD_ 64
#define BH_ (B_*NH_)     // 64
#define M_  (B_*T_)      // 8192

// Scratch (allocation-free device globals), all bf16 hi/lo split pairs
__device__ __nv_bfloat16 g_xh[M_*C_],      g_xl[M_*C_];        // x split
__device__ __nv_bfloat16 g_wqkvh[C_*3*C_], g_wqkvl[C_*3*C_];   // Wqkv split [K][N]
__device__ __nv_bfloat16 g_wph[C_*C_],     g_wpl[C_*C_];       // Wproj split [K][N]
__device__ __nv_bfloat16 g_qh[BH_*T_*HD_], g_ql[BH_*T_*HD_];   // [B,NH,T,HD]
__device__ __nv_bfloat16 g_kh[BH_*T_*HD_], g_kl[BH_*T_*HD_];
__device__ __nv_bfloat16 g_vh[BH_*T_*HD_], g_vl[BH_*T_*HD_];
__device__ __nv_bfloat16 g_yh[M_*C_],      g_yl[M_*C_];        // attention out split

__device__ __forceinline__ uint32_t smem_u32(const void* p) {
    return (uint32_t)__cvta_generic_to_shared(p);
}

#define LDSM4(R, ptr)                                                          \
    asm volatile("ldmatrix.sync.aligned.m8n8.x4.shared.b16 {%0,%1,%2,%3}, [%4];" \
                 : "=r"((R)[0]), "=r"((R)[1]), "=r"((R)[2]), "=r"((R)[3])      \
                 : "r"(smem_u32(ptr)))

#define LDSM4T(R, ptr)                                                         \
    asm volatile("ldmatrix.sync.aligned.m8n8.x4.trans.shared.b16 {%0,%1,%2,%3}, [%4];" \
                 : "=r"((R)[0]), "=r"((R)[1]), "=r"((R)[2]), "=r"((R)[3])      \
                 : "r"(smem_u32(ptr)))

#define MMA16816(D, A, b0, b1)                                                 \
    asm volatile("mma.sync.aligned.m16n8k16.row.col.f32.bf16.bf16.f32 "        \
                 "{%0,%1,%2,%3}, {%4,%5,%6,%7}, {%8,%9}, {%0,%1,%2,%3};"       \
                 : "+f"((D)[0]), "+f"((D)[1]), "+f"((D)[2]), "+f"((D)[3])      \
                 : "r"((A)[0]), "r"((A)[1]), "r"((A)[2]), "r"((A)[3]),         \
                   "r"(b0), "r"(b1))

__device__ __forceinline__ void cp16(uint32_t dst, const void* src) {
    asm volatile("cp.async.cg.shared.global [%0], [%1], 16;" :: "r"(dst), "l"(src));
}
#define CP_COMMIT() asm volatile("cp.async.commit_group;")
#define CP_WAIT0()  asm volatile("cp.async.wait_group 0;")
#define CP_WAIT1()  asm volatile("cp.async.wait_group 1;")

__device__ __forceinline__ void split_bf16(float x, __nv_bfloat16& h, __nv_bfloat16& l) {
    h = __float2bfloat16(x);
    l = __float2bfloat16(x - __bfloat162float(h));
}

__device__ __forceinline__ uint32_t pack2(float a, float b) {
    __nv_bfloat162 t = __halves2bfloat162(__float2bfloat16(a), __float2bfloat16(b));
    return *reinterpret_cast<uint32_t*>(&t);
}

// ---------------------------------------------------------------------------
// Elementwise fp32 -> bf16 hi/lo split
// ---------------------------------------------------------------------------
__global__ __launch_bounds__(256) void split_pass(
    const float* __restrict__ in, __nv_bfloat16* __restrict__ oh,
    __nv_bfloat16* __restrict__ ol, int n4)
{
    int i = blockIdx.x * blockDim.x + threadIdx.x;
    if (i >= n4) return;
    float4 v = reinterpret_cast<const float4*>(in)[i];
    __nv_bfloat16 h0, l0, h1, l1, h2, l2, h3, l3;
    split_bf16(v.x, h0, l0); split_bf16(v.y, h1, l1);
    split_bf16(v.z, h2, l2); split_bf16(v.w, h3, l3);
    reinterpret_cast<__nv_bfloat162*>(oh)[2*i]   = __halves2bfloat162(h0, h1);
    reinterpret_cast<__nv_bfloat162*>(oh)[2*i+1] = __halves2bfloat162(h2, h3);
    reinterpret_cast<__nv_bfloat162*>(ol)[2*i]   = __halves2bfloat162(l0, l1);
    reinterpret_cast<__nv_bfloat162*>(ol)[2*i+1] = __halves2bfloat162(l2, l3);
}

// ---------------------------------------------------------------------------
// GEMM on pre-split bf16 hi/lo, cp.async 3-stage pipeline, ONE sync per iter.
// Block 128x128, BK=32, 256 threads = 8 warps (4m x 2n), warp tile 32x64.
// MODE 0: A = g_x{h,l}, W = g_wqkv{h,l}; scatter into g_{q,k,v}{h,l}.
// MODE 1: A = g_y{h,l}, W = g_wp{h,l};  fp32 row-major output + bias.
// ---------------------------------------------------------------------------
template <int MODE>
__global__ __launch_bounds__(256, 2) void gemm_pre(
    const float* __restrict__ bias, float* __restrict__ Cout, int M, int N, int K)
{
    constexpr int LDA = 40;    // A smem stride (32+8), bf16
    constexpr int LDB = 136;   // B smem stride (128+8), bf16
    constexpr int ASZ = 128 * LDA;
    constexpr int BSZ = 32 * LDB;
    constexpr int STAGE = 2 * ASZ + 2 * BSZ;   // 18944 elems = 37888 B

    extern __shared__ __nv_bfloat16 smem[];

    const __nv_bfloat16* Agh = (MODE == 0) ? g_xh : g_yh;
    const __nv_bfloat16* Agl = (MODE == 0) ? g_xl : g_yl;
    const __nv_bfloat16* Wgh = (MODE == 0) ? g_wqkvh : g_wph;
    const __nv_bfloat16* Wgl = (MODE == 0) ? g_wqkvl : g_wpl;

    int tid  = threadIdx.x;
    int lane = tid & 31, warp = tid >> 5;
    int cRow = blockIdx.y, cCol = blockIdx.x;
    int warpM = warp & 3, warpN = warp >> 2;      // 4m x 2n
    int mr0 = warpM * 32;
    int n0w = warpN * 64;

    const __nv_bfloat16* Abh = Agh + (size_t)cRow * 128 * K;
    const __nv_bfloat16* Abl = Agl + (size_t)cRow * 128 * K;
    const __nv_bfloat16* Wbh = Wgh + cCol * 128;
    const __nv_bfloat16* Wbl = Wgl + cCol * 128;

    int ar0 = tid >> 2,  aq0 = (tid & 3) << 3;
    int ar1 = ar0 + 64;
    int br0 = tid >> 4,  bq0 = (tid & 15) << 3;
    int br1 = br0 + 16;

    uint32_t smem_base = smem_u32(smem);

    auto issue_stage = [&](int st, int k0) {
        uint32_t sb = smem_base + st * STAGE * 2;
        uint32_t ah = sb, al = sb + ASZ * 2, bh = sb + 2 * ASZ * 2, bl = sb + (2 * ASZ + BSZ) * 2;
        cp16(ah + (ar0 * LDA + aq0) * 2, Abh + (size_t)ar0 * K + k0 + aq0);
        cp16(ah + (ar1 * LDA + aq0) * 2, Abh + (size_t)ar1 * K + k0 + aq0);
        cp16(al + (ar0 * LDA + aq0) * 2, Abl + (size_t)ar0 * K + k0 + aq0);
        cp16(al + (ar1 * LDA + aq0) * 2, Abl + (size_t)ar1 * K + k0 + aq0);
        cp16(bh + (br0 * LDB + bq0) * 2, Wbh + (size_t)(k0 + br0) * N + bq0);
        cp16(bh + (br1 * LDB + bq0) * 2, Wbh + (size_t)(k0 + br1) * N + bq0);
        cp16(bl + (br0 * LDB + bq0) * 2, Wbl + (size_t)(k0 + br0) * N + bq0);
        cp16(bl + (br1 * LDB + bq0) * 2, Wbl + (size_t)(k0 + br1) * N + bq0);
    };

    float acc[2][8][4];
    #pragma unroll
    for (int i = 0; i < 2; i++)
        #pragma unroll
        for (int j = 0; j < 8; j++)
            #pragma unroll
            for (int q = 0; q < 4; q++) acc[i][j][q] = 0.f;

    issue_stage(0, 0);
    CP_COMMIT();
    issue_stage(1, 32);
    CP_COMMIT();

    int NT = K / 32;
    for (int it = 0; it < NT; it++) {
        CP_WAIT1();          // stage it complete (stage it+1 may be in flight)
        __syncthreads();     // data visible to all warps; all warps done with it-1
        if (it + 2 < NT) {
            issue_stage((it + 2) % 3, (it + 2) * 32);
            CP_COMMIT();
        }

        __nv_bfloat16* Ah = smem + (it % 3) * STAGE;
        __nv_bfloat16* Al = Ah + ASZ;
        __nv_bfloat16* Bh = Al + ASZ;
        __nv_bfloat16* Bl = Bh + BSZ;

        #pragma unroll
        for (int k16 = 0; k16 < 2; k16++) {
            int kk = k16 * 16;
            uint32_t ahf[2][4], alf[2][4], bhf[4][4], blf[4][4];

            #pragma unroll
            for (int mi = 0; mi < 2; mi++) {
                int off = (mr0 + mi * 16 + (lane & 15)) * LDA + kk + ((lane >> 4) << 3);
                LDSM4(ahf[mi], &Ah[off]);
                LDSM4(alf[mi], &Al[off]);
            }
            #pragma unroll
            for (int g = 0; g < 4; g++) {
                int r = kk + ((lane & 16) >> 1) + (lane & 7);
                int c = n0w + g * 16 + (lane & 8);
                int off = r * LDB + c;
                LDSM4T(bhf[g], &Bh[off]);
                LDSM4T(blf[g], &Bl[off]);
            }

            #pragma unroll
            for (int mi = 0; mi < 2; mi++) {
                #pragma unroll
                for (int nj = 0; nj < 8; nj++) {
                    int g = nj >> 1, h = nj & 1;
                    uint32_t b0h = h ? bhf[g][1] : bhf[g][0];
                    uint32_t b1h = h ? bhf[g][3] : bhf[g][2];
                    uint32_t b0l = h ? blf[g][1] : blf[g][0];
                    uint32_t b1l = h ? blf[g][3] : blf[g][2];
                    MMA16816(acc[mi][nj], ahf[mi], b0h, b1h);
                    MMA16816(acc[mi][nj], ahf[mi], b0l, b1l);
                    MMA16816(acc[mi][nj], alf[mi], b0h, b1h);
                }
            }
        }
        // no trailing sync: next iteration's top sync protects buffer reuse
    }

    // --- epilogue ---
    int rbase = cRow * 128 + mr0 + (lane >> 2);
    int cbase = cCol * 128 + n0w + ((lane & 3) << 1);

    #pragma unroll
    for (int mi = 0; mi < 2; mi++) {
        #pragma unroll
        for (int nj = 0; nj < 8; nj++) {
            int m0 = rbase + mi * 16;
            int n  = cbase + nj * 8;
            float bv0 = bias[n], bv1 = bias[n + 1];
            float v00 = acc[mi][nj][0] + bv0, v01 = acc[mi][nj][1] + bv1;
            float v10 = acc[mi][nj][2] + bv0, v11 = acc[mi][nj][3] + bv1;
            if (MODE == 1) {
                *reinterpret_cast<float2*>(&Cout[(size_t)m0 * N + n])       = make_float2(v00, v01);
                *reinterpret_cast<float2*>(&Cout[(size_t)(m0 + 8) * N + n]) = make_float2(v10, v11);
            } else {
                int which = n / C_;
                int c = n - which * C_;
                int h = c >> 6, d = c & 63;
                __nv_bfloat16* dh = (which == 0) ? g_qh : (which == 1) ? g_kh : g_vh;
                __nv_bfloat16* dl = (which == 0) ? g_ql : (which == 1) ? g_kl : g_vl;
                int b0i = m0 >> 11, t0 = m0 & 2047;
                int b1i = (m0 + 8) >> 11, t1 = (m0 + 8) & 2047;
                size_t i0 = (((size_t)b0i * NH_ + h) * T_ + t0) * HD_ + d;
                size_t i1 = (((size_t)b1i * NH_ + h) * T_ + t1) * HD_ + d;
                __nv_bfloat16 h00, l00, h01, l01, h10, l10, h11, l11;
                split_bf16(v00, h00, l00); split_bf16(v01, h01, l01);
                split_bf16(v10, h10, l10); split_bf16(v11, h11, l11);
                *reinterpret_cast<__nv_bfloat162*>(&dh[i0]) = __halves2bfloat162(h00, h01);
                *reinterpret_cast<__nv_bfloat162*>(&dl[i0]) = __halves2bfloat162(l00, l01);
                *reinterpret_cast<__nv_bfloat162*>(&dh[i1]) = __halves2bfloat162(h10, h11);
                *reinterpret_cast<__nv_bfloat162*>(&dl[i1]) = __halves2bfloat162(l10, l11);
            }
        }
    }
}

// ---------------------------------------------------------------------------
// Flash attention via tensor cores, causal. CTA: 128 q-rows, 64-key iters.
// 8 warps x 16 rows. bf16x3. K/V smem fills via cp.async.
// ---------------------------------------------------------------------------
__global__ __launch_bounds__(256) void flash_mma_kernel()
{
    constexpr int LDS_ = 72;
    extern __shared__ __nv_bfloat16 smf[];
    __nv_bfloat16* Qh = smf;
    __nv_bfloat16* Ql = Qh + 128 * LDS_;
    __nv_bfloat16* Kh = Ql + 128 * LDS_;
    __nv_bfloat16* Kl = Kh + 64 * LDS_;
    __nv_bfloat16* Vh = Kl + 64 * LDS_;
    __nv_bfloat16* Vl = Vh + 64 * LDS_;

    int bh = blockIdx.y;
    int qt = gridDim.x - 1 - blockIdx.x;
    int q0 = qt * 128;
    int tid = threadIdx.x;
    int warp = tid >> 5, lane = tid & 31;
    int wrow = warp * 16;
    int g = lane >> 2, t2 = (lane & 3) << 1;

    const __nv_bfloat16* Qgh = g_qh + ((size_t)bh * T_ + q0) * HD_;
    const __nv_bfloat16* Qgl = g_ql + ((size_t)bh * T_ + q0) * HD_;

    #pragma unroll
    for (int i = 0; i < 4; i++) {
        int idx = (tid + i * 256) * 8;
        int r = idx >> 6, c = idx & 63;
        cp16(smem_u32(&Qh[r * LDS_ + c]), &Qgh[r * 64 + c]);
        cp16(smem_u32(&Ql[r * LDS_ + c]), &Qgl[r * 64 + c]);
    }
    CP_COMMIT();

    float O[8][4];
    #pragma unroll
    for (int i = 0; i < 8; i++)
        #pragma unroll
        for (int q = 0; q < 4; q++) O[i][q] = 0.f;
    float m0 = -INFINITY, m1 = -INFINITY, l0 = 0.f, l1 = 0.f;

    const float scale = 0.125f;
    int row0 = q0 + wrow + g;
    int row1 = row0 + 8;

    CP_WAIT0();
    __syncthreads();

    int kt_max = 2 * qt + 1;
    for (int kt = 0; kt <= kt_max; kt++) {
        int k0 = kt * 64;

        {
            const __nv_bfloat16* kgh = g_kh + ((size_t)bh * T_ + k0) * HD_;
            const __nv_bfloat16* kgl = g_kl + ((size_t)bh * T_ + k0) * HD_;
            const __nv_bfloat16* vgh = g_vh + ((size_t)bh * T_ + k0) * HD_;
            const __nv_bfloat16* vgl = g_vl + ((size_t)bh * T_ + k0) * HD_;
            #pragma unroll
            for (int i = 0; i < 2; i++) {
                int idx = (tid + i * 256) * 8;
                int r = idx >> 6, c = idx & 63;
                cp16(smem_u32(&Kh[r * LDS_ + c]), &kgh[r * 64 + c]);
                cp16(smem_u32(&Kl[r * LDS_ + c]), &kgl[r * 64 + c]);
                cp16(smem_u32(&Vh[r * LDS_ + c]), &vgh[r * 64 + c]);
                cp16(smem_u32(&Vl[r * LDS_ + c]), &vgl[r * 64 + c]);
            }
            CP_COMMIT();
            CP_WAIT0();
        }
        __syncthreads();

        float S[8][4];
        #pragma unroll
        for (int j = 0; j < 8; j++)
            #pragma unroll
            for (int q = 0; q < 4; q++) S[j][q] = 0.f;

        #pragma unroll
        for (int ks = 0; ks < 4; ks++) {
            int kk = ks * 16;
            uint32_t qhf[4], qlf[4];
            {
                int off = (wrow + (lane & 15)) * LDS_ + kk + ((lane >> 4) << 3);
                LDSM4(qhf, &Qh[off]);
                LDSM4(qlf, &Ql[off]);
            }
            uint32_t bKh[8][2], bKl[8][2];
            #pragma unroll
            for (int tp = 0; tp < 4; tp++) {
                uint32_t R[4];
                int off = (tp * 16 + (lane & 7) + ((lane >> 4) << 3)) * LDS_
                          + kk + (((lane >> 3) & 1) << 3);
                LDSM4(R, &Kh[off]);
                bKh[2*tp][0] = R[0]; bKh[2*tp][1] = R[1];
                bKh[2*tp+1][0] = R[2]; bKh[2*tp+1][1] = R[3];
                LDSM4(R, &Kl[off]);
                bKl[2*tp][0] = R[0]; bKl[2*tp][1] = R[1];
                bKl[2*tp+1][0] = R[2]; bKl[2*tp+1][1] = R[3];
            }
            #pragma unroll
            for (int j = 0; j < 8; j++) {
                MMA16816(S[j], qhf, bKh[j][0], bKh[j][1]);
                MMA16816(S[j], qlf, bKh[j][0], bKh[j][1]);
                MMA16816(S[j], qhf, bKl[j][0], bKl[j][1]);
            }
        }

        if (kt >= 2 * qt) {
            #pragma unroll
            for (int j = 0; j < 8; j++) {
                int key = k0 + j * 8 + t2;
                if (key     > row0) S[j][0] = -1e30f;
                if (key + 1 > row0) S[j][1] = -1e30f;
                if (key     > row1) S[j][2] = -1e30f;
                if (key + 1 > row1) S[j][3] = -1e30f;
            }
        }

        float mx0 = -1e30f, mx1 = -1e30f;
        #pragma unroll
        for (int j = 0; j < 8; j++) {
            mx0 = fmaxf(mx0, fmaxf(S[j][0], S[j][1]));
            mx1 = fmaxf(mx1, fmaxf(S[j][2], S[j][3]));
        }
        #pragma unroll
        for (int off = 1; off <= 2; off <<= 1) {
            mx0 = fmaxf(mx0, __shfl_xor_sync(0xffffffffu, mx0, off));
            mx1 = fmaxf(mx1, __shfl_xor_sync(0xffffffffu, mx1, off));
        }
        float mn0 = fmaxf(m0, mx0 * scale);
        float mn1 = fmaxf(m1, mx1 * scale);
        float a0 = __expf(m0 - mn0);
        float a1 = __expf(m1 - mn1);
        m0 = mn0; m1 = mn1;

        float s0 = 0.f, s1 = 0.f;
        #pragma unroll
        for (int j = 0; j < 8; j++) {
            S[j][0] = __expf(fmaf(S[j][0], scale, -mn0));
            S[j][1] = __expf(fmaf(S[j][1], scale, -mn0));
            S[j][2] = __expf(fmaf(S[j][2], scale, -mn1));
            S[j][3] = __expf(fmaf(S[j][3], scale, -mn1));
            s0 += S[j][0] + S[j][1];
            s1 += S[j][2] + S[j][3];
        }
        #pragma unroll
        for (int off = 1; off <= 2; off <<= 1) {
            s0 += __shfl_xor_sync(0xffffffffu, s0, off);
            s1 += __shfl_xor_sync(0xffffffffu, s1, off);
        }
        l0 = l0 * a0 + s0;
        l1 = l1 * a1 + s1;
        #pragma unroll
        for (int i = 0; i < 8; i++) {
            O[i][0] *= a0; O[i][1] *= a0;
            O[i][2] *= a1; O[i][3] *= a1;
        }

        #pragma unroll
        for (int ks = 0; ks < 4; ks++) {
            int j0 = 2 * ks, j1 = 2 * ks + 1;
            uint32_t aPh[4], aPl[4];
            aPh[0] = pack2(S[j0][0], S[j0][1]);
            aPh[1] = pack2(S[j0][2], S[j0][3]);
            aPh[2] = pack2(S[j1][0], S[j1][1]);
            aPh[3] = pack2(S[j1][2], S[j1][3]);
            {
                __nv_bfloat162 h;
                h = *reinterpret_cast<__nv_bfloat162*>(&aPh[0]);
                aPl[0] = pack2(S[j0][0] - __low2float(h), S[j0][1] - __high2float(h));
                h = *reinterpret_cast<__nv_bfloat162*>(&aPh[1]);
                aPl[1] = pack2(S[j0][2] - __low2float(h), S[j0][3] - __high2float(h));
                h = *reinterpret_cast<__nv_bfloat162*>(&aPh[2]);
                aPl[2] = pack2(S[j1][0] - __low2float(h), S[j1][1] - __high2float(h));
                h = *reinterpret_cast<__nv_bfloat162*>(&aPh[3]);
                aPl[3] = pack2(S[j1][2] - __low2float(h), S[j1][3] - __high2float(h));
            }
            uint32_t Rh[4][4], Rl[4][4];
            #pragma unroll
            for (int gd = 0; gd < 4; gd++) {
                int off = (ks * 16 + ((lane & 16) >> 1) + (lane & 7)) * LDS_
                          + gd * 16 + (lane & 8);
                LDSM4T(Rh[gd], &Vh[off]);
                LDSM4T(Rl[gd], &Vl[off]);
            }
            #pragma unroll
            for (int gd = 0; gd < 4; gd++) {
                MMA16816(O[gd*2+0], aPh, Rh[gd][0], Rh[gd][2]);
                MMA16816(O[gd*2+1], aPh, Rh[gd][1], Rh[gd][3]);
                MMA16816(O[gd*2+0], aPl, Rh[gd][0], Rh[gd][2]);
                MMA16816(O[gd*2+1], aPl, Rh[gd][1], Rh[gd][3]);
                MMA16816(O[gd*2+0], aPh, Rl[gd][0], Rl[gd][2]);
                MMA16816(O[gd*2+1], aPh, Rl[gd][1], Rl[gd][3]);
            }
        }
        __syncthreads();
    }

    int b = bh >> 4, h = bh & 15;
    float inv0 = 1.f / l0, inv1 = 1.f / l1;
    size_t base0 = ((size_t)b * T_ + row0) * C_ + h * 64 + t2;
    size_t base1 = ((size_t)b * T_ + row1) * C_ + h * 64 + t2;
    #pragma unroll
    for (int i = 0; i < 8; i++) {
        float v0 = O[i][0] * inv0, v1 = O[i][1] * inv0;
        float v2 = O[i][2] * inv1, v3 = O[i][3] * inv1;
        __nv_bfloat16 h0, l0b, h1, l1b, h2, l2b, h3, l3b;
        split_bf16(v0, h0, l0b); split_bf16(v1, h1, l1b);
        split_bf16(v2, h2, l2b); split_bf16(v3, h3, l3b);
        *reinterpret_cast<__nv_bfloat162*>(&g_yh[base0 + i * 8]) = __halves2bfloat162(h0, h1);
        *reinterpret_cast<__nv_bfloat162*>(&g_yl[base0 + i * 8]) = __halves2bfloat162(l0b, l1b);
        *reinterpret_cast<__nv_bfloat162*>(&g_yh[base1 + i * 8]) = __halves2bfloat162(h2, h3);
        *reinterpret_cast<__nv_bfloat162*>(&g_yl[base1 + i * 8]) = __halves2bfloat162(l2b, l3b);
    }
}

// ---------------------------------------------------------------------------
extern "C" void kernel_launch(void* const* d_in, const int* in_sizes, int n_in,
                              void* d_out, int out_size)
{
    const float* x     = (const float*)d_in[0];
    const float* Wqkv  = (const float*)d_in[1];
    const float* bqkv  = (const float*)d_in[2];
    const float* Wproj = (const float*)d_in[3];
    const float* bproj = (const float*)d_in[4];
    float* out = (float*)d_out;

    static __nv_bfloat16 *xh_p = nullptr, *xl_p, *wqh_p, *wql_p, *wph_p, *wpl_p;
    if (!xh_p) {
        cudaGetSymbolAddress((void**)&xh_p,  g_xh);
        cudaGetSymbolAddress((void**)&xl_p,  g_xl);
        cudaGetSymbolAddress((void**)&wqh_p, g_wqkvh);
        cudaGetSymbolAddress((void**)&wql_p, g_wqkvl);
        cudaGetSymbolAddress((void**)&wph_p, g_wph);
        cudaGetSymbolAddress((void**)&wpl_p, g_wpl);
    }

    // 0) Pre-split fp32 inputs into bf16 hi/lo
    split_pass<<<(M_ * C_ / 4 + 255) / 256, 256>>>(x, xh_p, xl_p, M_ * C_ / 4);
    split_pass<<<(C_ * 3 * C_ / 4 + 255) / 256, 256>>>(Wqkv, wqh_p, wql_p, C_ * 3 * C_ / 4);
    split_pass<<<(C_ * C_ / 4 + 255) / 256, 256>>>(Wproj, wph_p, wpl_p, C_ * C_ / 4);

    const int gemm_smem = 3 * (2 * 128 * 40 + 2 * 32 * 136) * (int)sizeof(__nv_bfloat16); // 113664

    // 1) QKV GEMM -> bf16 hi/lo Q,K,V
    {
        cudaFuncSetAttribute(gemm_pre<0>, cudaFuncAttributeMaxDynamicSharedMemorySize, gemm_smem);
        dim3 grid(3072 / 128, 8192 / 128);
        gemm_pre<0><<<grid, 256, gemm_smem>>>(bqkv, nullptr, M_, 3 * C_, C_);
    }

    // 2) Flash attention (tensor cores), writes g_yh/g_yl
    {
        const int smem = (2 * 128 * 72 + 4 * 64 * 72) * (int)sizeof(__nv_bfloat16); // 73728
        cudaFuncSetAttribute(flash_mma_kernel, cudaFuncAttributeMaxDynamicSharedMemorySize, smem);
        flash_mma_kernel<<<dim3(16, 64), 256, smem>>>();
    }

    // 3) Projection GEMM: y @ Wproj + bproj -> out
    {
        cudaFuncSetAttribute(gemm_pre<1>, cudaFuncAttributeMaxDynamicSharedMemorySize, gemm_smem);
        dim3 grid(1024 / 128, 8192 / 128);
        gemm_pre<1><<<grid, 256, gemm_smem>>>(bproj, out, M_, C_, C_);
    }
}

// round 12
// speedup vs baseline: 1.1271x; 1.0217x over previous
#include <cuda_runtime.h>
#include <cuda_bf16.h>
#include <math.h>
#include <stdint.h>

// Problem constants
#define B_  4
#define T_  2048
#define C_  1024
#define NH_ 16
#define HD_ 64
#define BH_ (B_*NH_)     // 64
#define M_  (B_*T_)      // 8192

// Scratch (allocation-free device globals), all bf16 hi/lo split pairs
__device__ __nv_bfloat16 g_xh[M_*C_],      g_xl[M_*C_];        // x split
__device__ __nv_bfloat16 g_wqkvh[C_*3*C_], g_wqkvl[C_*3*C_];   // Wqkv split [K][N]
__device__ __nv_bfloat16 g_wph[C_*C_],     g_wpl[C_*C_];       // Wproj split [K][N]
__device__ __nv_bfloat16 g_qh[BH_*T_*HD_], g_ql[BH_*T_*HD_];   // [B,NH,T,HD]
__device__ __nv_bfloat16 g_kh[BH_*T_*HD_], g_kl[BH_*T_*HD_];
__device__ __nv_bfloat16 g_vh[BH_*T_*HD_], g_vl[BH_*T_*HD_];
__device__ __nv_bfloat16 g_yh[M_*C_],      g_yl[M_*C_];        // attention out split

__device__ __forceinline__ uint32_t smem_u32(const void* p) {
    return (uint32_t)__cvta_generic_to_shared(p);
}

#define LDSM4(R, ptr)                                                          \
    asm volatile("ldmatrix.sync.aligned.m8n8.x4.shared.b16 {%0,%1,%2,%3}, [%4];" \
                 : "=r"((R)[0]), "=r"((R)[1]), "=r"((R)[2]), "=r"((R)[3])      \
                 : "r"(smem_u32(ptr)))

#define LDSM4T(R, ptr)                                                         \
    asm volatile("ldmatrix.sync.aligned.m8n8.x4.trans.shared.b16 {%0,%1,%2,%3}, [%4];" \
                 : "=r"((R)[0]), "=r"((R)[1]), "=r"((R)[2]), "=r"((R)[3])      \
                 : "r"(smem_u32(ptr)))

#define MMA16816(D, A, b0, b1)                                                 \
    asm volatile("mma.sync.aligned.m16n8k16.row.col.f32.bf16.bf16.f32 "        \
                 "{%0,%1,%2,%3}, {%4,%5,%6,%7}, {%8,%9}, {%0,%1,%2,%3};"       \
                 : "+f"((D)[0]), "+f"((D)[1]), "+f"((D)[2]), "+f"((D)[3])      \
                 : "r"((A)[0]), "r"((A)[1]), "r"((A)[2]), "r"((A)[3]),         \
                   "r"(b0), "r"(b1))

__device__ __forceinline__ void cp16(uint32_t dst, const void* src) {
    asm volatile("cp.async.cg.shared.global [%0], [%1], 16;" :: "r"(dst), "l"(src));
}
#define CP_COMMIT() asm volatile("cp.async.commit_group;")
#define CP_WAIT0()  asm volatile("cp.async.wait_group 0;")

__device__ __forceinline__ void split_bf16(float x, __nv_bfloat16& h, __nv_bfloat16& l) {
    h = __float2bfloat16(x);
    l = __float2bfloat16(x - __bfloat162float(h));
}

__device__ __forceinline__ uint32_t pack2(float a, float b) {
    __nv_bfloat162 t = __halves2bfloat162(__float2bfloat16(a), __float2bfloat16(b));
    return *reinterpret_cast<uint32_t*>(&t);
}

// ---------------------------------------------------------------------------
// Elementwise fp32 -> bf16 hi/lo split
// ---------------------------------------------------------------------------
__global__ __launch_bounds__(256) void split_pass(
    const float* __restrict__ in, __nv_bfloat16* __restrict__ oh,
    __nv_bfloat16* __restrict__ ol, int n4)
{
    int i = blockIdx.x * blockDim.x + threadIdx.x;
    if (i >= n4) return;
    float4 v = reinterpret_cast<const float4*>(in)[i];
    __nv_bfloat16 h0, l0, h1, l1, h2, l2, h3, l3;
    split_bf16(v.x, h0, l0); split_bf16(v.y, h1, l1);
    split_bf16(v.z, h2, l2); split_bf16(v.w, h3, l3);
    reinterpret_cast<__nv_bfloat162*>(oh)[2*i]   = __halves2bfloat162(h0, h1);
    reinterpret_cast<__nv_bfloat162*>(oh)[2*i+1] = __halves2bfloat162(h2, h3);
    reinterpret_cast<__nv_bfloat162*>(ol)[2*i]   = __halves2bfloat162(l0, l1);
    reinterpret_cast<__nv_bfloat162*>(ol)[2*i+1] = __halves2bfloat162(l2, l3);
}

// ---------------------------------------------------------------------------
// GEMM on pre-split bf16 hi/lo, cp.async 2-stage, block tile 128x64 for
// 3 CTAs/SM occupancy. 256 threads = 8 warps (4m x 2n), warp tile 32x32.
// MODE 0: A = g_x{h,l}, W = g_wqkv{h,l}; scatter into g_{q,k,v}{h,l}.
// MODE 1: A = g_y{h,l}, W = g_wp{h,l};  fp32 row-major output + bias.
// ---------------------------------------------------------------------------
template <int MODE>
__global__ __launch_bounds__(256, 3) void gemm_pre(
    const float* __restrict__ bias, float* __restrict__ Cout, int M, int N, int K)
{
    constexpr int LDA = 40;    // A smem stride (32+8), bf16
    constexpr int LDB = 72;    // B smem stride (64+8), bf16
    constexpr int ASZ = 128 * LDA;          // 5120
    constexpr int BSZ = 32 * LDB;           // 2304
    constexpr int STAGE = 2 * ASZ + 2 * BSZ; // 14848 elems = 29696 B

    extern __shared__ __nv_bfloat16 smem[];

    const __nv_bfloat16* Agh = (MODE == 0) ? g_xh : g_yh;
    const __nv_bfloat16* Agl = (MODE == 0) ? g_xl : g_yl;
    const __nv_bfloat16* Wgh = (MODE == 0) ? g_wqkvh : g_wph;
    const __nv_bfloat16* Wgl = (MODE == 0) ? g_wqkvl : g_wpl;

    int tid  = threadIdx.x;
    int lane = tid & 31, warp = tid >> 5;
    int cRow = blockIdx.y, cCol = blockIdx.x;
    int warpM = warp & 3, warpN = warp >> 2;      // 4m x 2n
    int mr0 = warpM * 32;
    int n0w = warpN * 32;

    const __nv_bfloat16* Abh = Agh + (size_t)cRow * 128 * K;
    const __nv_bfloat16* Abl = Agl + (size_t)cRow * 128 * K;
    const __nv_bfloat16* Wbh = Wgh + cCol * 64;
    const __nv_bfloat16* Wbl = Wgl + cCol * 64;

    int ar0 = tid >> 2,  aq0 = (tid & 3) << 3;    // A: 64 rows/pass, 2 passes
    int ar1 = ar0 + 64;
    int br0 = tid >> 3,  bq0 = (tid & 7) << 3;    // B: 32 rows x 64 cols, 1 pass

    uint32_t smem_base = smem_u32(smem);

    auto issue_stage = [&](int st, int k0) {
        uint32_t sb = smem_base + st * STAGE * 2;
        uint32_t ah = sb, al = sb + ASZ * 2, bh = sb + 2 * ASZ * 2, bl = sb + (2 * ASZ + BSZ) * 2;
        cp16(ah + (ar0 * LDA + aq0) * 2, Abh + (size_t)ar0 * K + k0 + aq0);
        cp16(ah + (ar1 * LDA + aq0) * 2, Abh + (size_t)ar1 * K + k0 + aq0);
        cp16(al + (ar0 * LDA + aq0) * 2, Abl + (size_t)ar0 * K + k0 + aq0);
        cp16(al + (ar1 * LDA + aq0) * 2, Abl + (size_t)ar1 * K + k0 + aq0);
        cp16(bh + (br0 * LDB + bq0) * 2, Wbh + (size_t)(k0 + br0) * N + bq0);
        cp16(bl + (br0 * LDB + bq0) * 2, Wbl + (size_t)(k0 + br0) * N + bq0);
    };

    float acc[2][4][4];    // [mi][nj][frag] : warp tile 32x32
    #pragma unroll
    for (int i = 0; i < 2; i++)
        #pragma unroll
        for (int j = 0; j < 4; j++)
            #pragma unroll
            for (int q = 0; q < 4; q++) acc[i][j][q] = 0.f;

    issue_stage(0, 0);
    CP_COMMIT();

    int NT = K / 32;
    for (int it = 0; it < NT; it++) {
        CP_WAIT0();
        __syncthreads();
        if (it + 1 < NT) {
            issue_stage((it + 1) & 1, (it + 1) * 32);
            CP_COMMIT();
        }

        __nv_bfloat16* Ah = smem + (it & 1) * STAGE;
        __nv_bfloat16* Al = Ah + ASZ;
        __nv_bfloat16* Bh = Al + ASZ;
        __nv_bfloat16* Bl = Bh + BSZ;

        #pragma unroll
        for (int k16 = 0; k16 < 2; k16++) {
            int kk = k16 * 16;
            uint32_t ahf[2][4], alf[2][4], bhf[2][4], blf[2][4];

            #pragma unroll
            for (int mi = 0; mi < 2; mi++) {
                int off = (mr0 + mi * 16 + (lane & 15)) * LDA + kk + ((lane >> 4) << 3);
                LDSM4(ahf[mi], &Ah[off]);
                LDSM4(alf[mi], &Al[off]);
            }
            #pragma unroll
            for (int g = 0; g < 2; g++) {
                int r = kk + ((lane & 16) >> 1) + (lane & 7);
                int c = n0w + g * 16 + (lane & 8);
                int off = r * LDB + c;
                LDSM4T(bhf[g], &Bh[off]);
                LDSM4T(blf[g], &Bl[off]);
            }

            #pragma unroll
            for (int mi = 0; mi < 2; mi++)
                #pragma unroll
                for (int nj = 0; nj < 4; nj++) {
                    int g = nj >> 1, h = nj & 1;
                    uint32_t b0h = h ? bhf[g][1] : bhf[g][0];
                    uint32_t b1h = h ? bhf[g][3] : bhf[g][2];
                    uint32_t b0l = h ? blf[g][1] : blf[g][0];
                    uint32_t b1l = h ? blf[g][3] : blf[g][2];
                    MMA16816(acc[mi][nj], ahf[mi], b0h, b1h);
                    MMA16816(acc[mi][nj], ahf[mi], b0l, b1l);
                    MMA16816(acc[mi][nj], alf[mi], b0h, b1h);
                }
        }
    }

    // --- epilogue ---
    int rbase = cRow * 128 + mr0 + (lane >> 2);
    int cbase = cCol * 64 + n0w + ((lane & 3) << 1);

    #pragma unroll
    for (int mi = 0; mi < 2; mi++) {
        #pragma unroll
        for (int nj = 0; nj < 4; nj++) {
            int m0 = rbase + mi * 16;
            int n  = cbase + nj * 8;
            float bv0 = bias[n], bv1 = bias[n + 1];
            float v00 = acc[mi][nj][0] + bv0, v01 = acc[mi][nj][1] + bv1;
            float v10 = acc[mi][nj][2] + bv0, v11 = acc[mi][nj][3] + bv1;
            if (MODE == 1) {
                *reinterpret_cast<float2*>(&Cout[(size_t)m0 * N + n])       = make_float2(v00, v01);
                *reinterpret_cast<float2*>(&Cout[(size_t)(m0 + 8) * N + n]) = make_float2(v10, v11);
            } else {
                int which = n / C_;
                int c = n - which * C_;
                int h = c >> 6, d = c & 63;
                __nv_bfloat16* dh = (which == 0) ? g_qh : (which == 1) ? g_kh : g_vh;
                __nv_bfloat16* dl = (which == 0) ? g_ql : (which == 1) ? g_kl : g_vl;
                int b0i = m0 >> 11, t0 = m0 & 2047;
                int b1i = (m0 + 8) >> 11, t1 = (m0 + 8) & 2047;
                size_t i0 = (((size_t)b0i * NH_ + h) * T_ + t0) * HD_ + d;
                size_t i1 = (((size_t)b1i * NH_ + h) * T_ + t1) * HD_ + d;
                __nv_bfloat16 h00, l00, h01, l01, h10, l10, h11, l11;
                split_bf16(v00, h00, l00); split_bf16(v01, h01, l01);
                split_bf16(v10, h10, l10); split_bf16(v11, h11, l11);
                *reinterpret_cast<__nv_bfloat162*>(&dh[i0]) = __halves2bfloat162(h00, h01);
                *reinterpret_cast<__nv_bfloat162*>(&dl[i0]) = __halves2bfloat162(l00, l01);
                *reinterpret_cast<__nv_bfloat162*>(&dh[i1]) = __halves2bfloat162(h10, h11);
                *reinterpret_cast<__nv_bfloat162*>(&dl[i1]) = __halves2bfloat162(l10, l11);
            }
        }
    }
}

// ---------------------------------------------------------------------------
// Flash attention via tensor cores, causal. CTA: 128 q-rows, 64-key iters.
// 8 warps x 16 rows. bf16x3. (unchanged from R9)
// ---------------------------------------------------------------------------
__global__ __launch_bounds__(256) void flash_mma_kernel()
{
    constexpr int LDS_ = 72;
    extern __shared__ __nv_bfloat16 smf[];
    __nv_bfloat16* Qh = smf;
    __nv_bfloat16* Ql = Qh + 128 * LDS_;
    __nv_bfloat16* Kh = Ql + 128 * LDS_;
    __nv_bfloat16* Kl = Kh + 64 * LDS_;
    __nv_bfloat16* Vh = Kl + 64 * LDS_;
    __nv_bfloat16* Vl = Vh + 64 * LDS_;

    int bh = blockIdx.y;
    int qt = gridDim.x - 1 - blockIdx.x;
    int q0 = qt * 128;
    int tid = threadIdx.x;
    int warp = tid >> 5, lane = tid & 31;
    int wrow = warp * 16;
    int g = lane >> 2, t2 = (lane & 3) << 1;

    const __nv_bfloat16* Qgh = g_qh + ((size_t)bh * T_ + q0) * HD_;
    const __nv_bfloat16* Qgl = g_ql + ((size_t)bh * T_ + q0) * HD_;

    #pragma unroll
    for (int i = 0; i < 4; i++) {
        int idx = (tid + i * 256) * 8;
        int r = idx >> 6, c = idx & 63;
        cp16(smem_u32(&Qh[r * LDS_ + c]), &Qgh[r * 64 + c]);
        cp16(smem_u32(&Ql[r * LDS_ + c]), &Qgl[r * 64 + c]);
    }
    CP_COMMIT();

    float O[8][4];
    #pragma unroll
    for (int i = 0; i < 8; i++)
        #pragma unroll
        for (int q = 0; q < 4; q++) O[i][q] = 0.f;
    float m0 = -INFINITY, m1 = -INFINITY, l0 = 0.f, l1 = 0.f;

    const float scale = 0.125f;
    int row0 = q0 + wrow + g;
    int row1 = row0 + 8;

    CP_WAIT0();
    __syncthreads();

    int kt_max = 2 * qt + 1;
    for (int kt = 0; kt <= kt_max; kt++) {
        int k0 = kt * 64;

        {
            const __nv_bfloat16* kgh = g_kh + ((size_t)bh * T_ + k0) * HD_;
            const __nv_bfloat16* kgl = g_kl + ((size_t)bh * T_ + k0) * HD_;
            const __nv_bfloat16* vgh = g_vh + ((size_t)bh * T_ + k0) * HD_;
            const __nv_bfloat16* vgl = g_vl + ((size_t)bh * T_ + k0) * HD_;
            #pragma unroll
            for (int i = 0; i < 2; i++) {
                int idx = (tid + i * 256) * 8;
                int r = idx >> 6, c = idx & 63;
                cp16(smem_u32(&Kh[r * LDS_ + c]), &kgh[r * 64 + c]);
                cp16(smem_u32(&Kl[r * LDS_ + c]), &kgl[r * 64 + c]);
                cp16(smem_u32(&Vh[r * LDS_ + c]), &vgh[r * 64 + c]);
                cp16(smem_u32(&Vl[r * LDS_ + c]), &vgl[r * 64 + c]);
            }
            CP_COMMIT();
            CP_WAIT0();
        }
        __syncthreads();

        float S[8][4];
        #pragma unroll
        for (int j = 0; j < 8; j++)
            #pragma unroll
            for (int q = 0; q < 4; q++) S[j][q] = 0.f;

        #pragma unroll
        for (int ks = 0; ks < 4; ks++) {
            int kk = ks * 16;
            uint32_t qhf[4], qlf[4];
            {
                int off = (wrow + (lane & 15)) * LDS_ + kk + ((lane >> 4) << 3);
                LDSM4(qhf, &Qh[off]);
                LDSM4(qlf, &Ql[off]);
            }
            uint32_t bKh[8][2], bKl[8][2];
            #pragma unroll
            for (int tp = 0; tp < 4; tp++) {
                uint32_t R[4];
                int off = (tp * 16 + (lane & 7) + ((lane >> 4) << 3)) * LDS_
                          + kk + (((lane >> 3) & 1) << 3);
                LDSM4(R, &Kh[off]);
                bKh[2*tp][0] = R[0]; bKh[2*tp][1] = R[1];
                bKh[2*tp+1][0] = R[2]; bKh[2*tp+1][1] = R[3];
                LDSM4(R, &Kl[off]);
                bKl[2*tp][0] = R[0]; bKl[2*tp][1] = R[1];
                bKl[2*tp+1][0] = R[2]; bKl[2*tp+1][1] = R[3];
            }
            #pragma unroll
            for (int j = 0; j < 8; j++) {
                MMA16816(S[j], qhf, bKh[j][0], bKh[j][1]);
                MMA16816(S[j], qlf, bKh[j][0], bKh[j][1]);
                MMA16816(S[j], qhf, bKl[j][0], bKl[j][1]);
            }
        }

        if (kt >= 2 * qt) {
            #pragma unroll
            for (int j = 0; j < 8; j++) {
                int key = k0 + j * 8 + t2;
                if (key     > row0) S[j][0] = -1e30f;
                if (key + 1 > row0) S[j][1] = -1e30f;
                if (key     > row1) S[j][2] = -1e30f;
                if (key + 1 > row1) S[j][3] = -1e30f;
            }
        }

        float mx0 = -1e30f, mx1 = -1e30f;
        #pragma unroll
        for (int j = 0; j < 8; j++) {
            mx0 = fmaxf(mx0, fmaxf(S[j][0], S[j][1]));
            mx1 = fmaxf(mx1, fmaxf(S[j][2], S[j][3]));
        }
        #pragma unroll
        for (int off = 1; off <= 2; off <<= 1) {
            mx0 = fmaxf(mx0, __shfl_xor_sync(0xffffffffu, mx0, off));
            mx1 = fmaxf(mx1, __shfl_xor_sync(0xffffffffu, mx1, off));
        }
        float mn0 = fmaxf(m0, mx0 * scale);
        float mn1 = fmaxf(m1, mx1 * scale);
        float a0 = __expf(m0 - mn0);
        float a1 = __expf(m1 - mn1);
        m0 = mn0; m1 = mn1;

        float s0 = 0.f, s1 = 0.f;
        #pragma unroll
        for (int j = 0; j < 8; j++) {
            S[j][0] = __expf(fmaf(S[j][0], scale, -mn0));
            S[j][1] = __expf(fmaf(S[j][1], scale, -mn0));
            S[j][2] = __expf(fmaf(S[j][2], scale, -mn1));
            S[j][3] = __expf(fmaf(S[j][3], scale, -mn1));
            s0 += S[j][0] + S[j][1];
            s1 += S[j][2] + S[j][3];
        }
        #pragma unroll
        for (int off = 1; off <= 2; off <<= 1) {
            s0 += __shfl_xor_sync(0xffffffffu, s0, off);
            s1 += __shfl_xor_sync(0xffffffffu, s1, off);
        }
        l0 = l0 * a0 + s0;
        l1 = l1 * a1 + s1;
        #pragma unroll
        for (int i = 0; i < 8; i++) {
            O[i][0] *= a0; O[i][1] *= a0;
            O[i][2] *= a1; O[i][3] *= a1;
        }

        #pragma unroll
        for (int ks = 0; ks < 4; ks++) {
            int j0 = 2 * ks, j1 = 2 * ks + 1;
            uint32_t aPh[4], aPl[4];
            aPh[0] = pack2(S[j0][0], S[j0][1]);
            aPh[1] = pack2(S[j0][2], S[j0][3]);
            aPh[2] = pack2(S[j1][0], S[j1][1]);
            aPh[3] = pack2(S[j1][2], S[j1][3]);
            {
                __nv_bfloat162 h;
                h = *reinterpret_cast<__nv_bfloat162*>(&aPh[0]);
                aPl[0] = pack2(S[j0][0] - __low2float(h), S[j0][1] - __high2float(h));
                h = *reinterpret_cast<__nv_bfloat162*>(&aPh[1]);
                aPl[1] = pack2(S[j0][2] - __low2float(h), S[j0][3] - __high2float(h));
                h = *reinterpret_cast<__nv_bfloat162*>(&aPh[2]);
                aPl[2] = pack2(S[j1][0] - __low2float(h), S[j1][1] - __high2float(h));
                h = *reinterpret_cast<__nv_bfloat162*>(&aPh[3]);
                aPl[3] = pack2(S[j1][2] - __low2float(h), S[j1][3] - __high2float(h));
            }
            uint32_t Rh[4][4], Rl[4][4];
            #pragma unroll
            for (int gd = 0; gd < 4; gd++) {
                int off = (ks * 16 + ((lane & 16) >> 1) + (lane & 7)) * LDS_
                          + gd * 16 + (lane & 8);
                LDSM4T(Rh[gd], &Vh[off]);
                LDSM4T(Rl[gd], &Vl[off]);
            }
            #pragma unroll
            for (int gd = 0; gd < 4; gd++) {
                MMA16816(O[gd*2+0], aPh, Rh[gd][0], Rh[gd][2]);
                MMA16816(O[gd*2+1], aPh, Rh[gd][1], Rh[gd][3]);
                MMA16816(O[gd*2+0], aPl, Rh[gd][0], Rh[gd][2]);
                MMA16816(O[gd*2+1], aPl, Rh[gd][1], Rh[gd][3]);
                MMA16816(O[gd*2+0], aPh, Rl[gd][0], Rl[gd][2]);
                MMA16816(O[gd*2+1], aPh, Rl[gd][1], Rl[gd][3]);
            }
        }
        __syncthreads();
    }

    int b = bh >> 4, h = bh & 15;
    float inv0 = 1.f / l0, inv1 = 1.f / l1;
    size_t base0 = ((size_t)b * T_ + row0) * C_ + h * 64 + t2;
    size_t base1 = ((size_t)b * T_ + row1) * C_ + h * 64 + t2;
    #pragma unroll
    for (int i = 0; i < 8; i++) {
        float v0 = O[i][0] * inv0, v1 = O[i][1] * inv0;
        float v2 = O[i][2] * inv1, v3 = O[i][3] * inv1;
        __nv_bfloat16 h0, l0b, h1, l1b, h2, l2b, h3, l3b;
        split_bf16(v0, h0, l0b); split_bf16(v1, h1, l1b);
        split_bf16(v2, h2, l2b); split_bf16(v3, h3, l3b);
        *reinterpret_cast<__nv_bfloat162*>(&g_yh[base0 + i * 8]) = __halves2bfloat162(h0, h1);
        *reinterpret_cast<__nv_bfloat162*>(&g_yl[base0 + i * 8]) = __halves2bfloat162(l0b, l1b);
        *reinterpret_cast<__nv_bfloat162*>(&g_yh[base1 + i * 8]) = __halves2bfloat162(h2, h3);
        *reinterpret_cast<__nv_bfloat162*>(&g_yl[base1 + i * 8]) = __halves2bfloat162(l2b, l3b);
    }
}

// ---------------------------------------------------------------------------
extern "C" void kernel_launch(void* const* d_in, const int* in_sizes, int n_in,
                              void* d_out, int out_size)
{
    const float* x     = (const float*)d_in[0];
    const float* Wqkv  = (const float*)d_in[1];
    const float* bqkv  = (const float*)d_in[2];
    const float* Wproj = (const float*)d_in[3];
    const float* bproj = (const float*)d_in[4];
    float* out = (float*)d_out;

    static __nv_bfloat16 *xh_p = nullptr, *xl_p, *wqh_p, *wql_p, *wph_p, *wpl_p;
    if (!xh_p) {
        cudaGetSymbolAddress((void**)&xh_p,  g_xh);
        cudaGetSymbolAddress((void**)&xl_p,  g_xl);
        cudaGetSymbolAddress((void**)&wqh_p, g_wqkvh);
        cudaGetSymbolAddress((void**)&wql_p, g_wqkvl);
        cudaGetSymbolAddress((void**)&wph_p, g_wph);
        cudaGetSymbolAddress((void**)&wpl_p, g_wpl);
    }

    // 0) Pre-split fp32 inputs into bf16 hi/lo
    split_pass<<<(M_ * C_ / 4 + 255) / 256, 256>>>(x, xh_p, xl_p, M_ * C_ / 4);
    split_pass<<<(C_ * 3 * C_ / 4 + 255) / 256, 256>>>(Wqkv, wqh_p, wql_p, C_ * 3 * C_ / 4);
    split_pass<<<(C_ * C_ / 4 + 255) / 256, 256>>>(Wproj, wph_p, wpl_p, C_ * C_ / 4);

    const int gemm_smem = 2 * (2 * 128 * 40 + 2 * 32 * 72) * (int)sizeof(__nv_bfloat16); // 59392

    // 1) QKV GEMM -> bf16 hi/lo Q,K,V
    {
        cudaFuncSetAttribute(gemm_pre<0>, cudaFuncAttributeMaxDynamicSharedMemorySize, gemm_smem);
        dim3 grid(3072 / 64, 8192 / 128);
        gemm_pre<0><<<grid, 256, gemm_smem>>>(bqkv, nullptr, M_, 3 * C_, C_);
    }

    // 2) Flash attention (tensor cores), writes g_yh/g_yl
    {
        const int smem = (2 * 128 * 72 + 4 * 64 * 72) * (int)sizeof(__nv_bfloat16); // 73728
        cudaFuncSetAttribute(flash_mma_kernel, cudaFuncAttributeMaxDynamicSharedMemorySize, smem);
        flash_mma_kernel<<<dim3(16, 64), 256, smem>>>();
    }

    // 3) Projection GEMM: y @ Wproj + bproj -> out
    {
        cudaFuncSetAttribute(gemm_pre<1>, cudaFuncAttributeMaxDynamicSharedMemorySize, gemm_smem);
        dim3 grid(1024 / 64, 8192 / 128);
        gemm_pre<1><<<grid, 256, gemm_smem>>>(bproj, out, M_, C_, C_);
    }
}

// round 13
// speedup vs baseline: 1.1274x; 1.0002x over previous
#include <cuda_runtime.h>
#include <cuda_bf16.h>
#include <math.h>
#include <stdint.h>

// Problem constants
#define B_  4
#define T_  2048
#define C_  1024
#define NH_ 16
#define HD_ 64
#define BH_ (B_*NH_)     // 64
#define M_  (B_*T_)      // 8192

// Scratch (allocation-free device globals), all bf16 hi/lo split pairs
__device__ __nv_bfloat16 g_xh[M_*C_],      g_xl[M_*C_];        // x split
__device__ __nv_bfloat16 g_wqkvh[C_*3*C_], g_wqkvl[C_*3*C_];   // Wqkv split [K][N]
__device__ __nv_bfloat16 g_wph[C_*C_],     g_wpl[C_*C_];       // Wproj split [K][N]
__device__ __nv_bfloat16 g_qh[BH_*T_*HD_], g_ql[BH_*T_*HD_];   // [B,NH,T,HD]
__device__ __nv_bfloat16 g_kh[BH_*T_*HD_], g_kl[BH_*T_*HD_];
__device__ __nv_bfloat16 g_vh[BH_*T_*HD_], g_vl[BH_*T_*HD_];
__device__ __nv_bfloat16 g_yh[M_*C_],      g_yl[M_*C_];        // attention out split

__device__ __forceinline__ uint32_t smem_u32(const void* p) {
    return (uint32_t)__cvta_generic_to_shared(p);
}

#define LDSM4(R, ptr)                                                          \
    asm volatile("ldmatrix.sync.aligned.m8n8.x4.shared.b16 {%0,%1,%2,%3}, [%4];" \
                 : "=r"((R)[0]), "=r"((R)[1]), "=r"((R)[2]), "=r"((R)[3])      \
                 : "r"(smem_u32(ptr)))

#define LDSM4T(R, ptr)                                                         \
    asm volatile("ldmatrix.sync.aligned.m8n8.x4.trans.shared.b16 {%0,%1,%2,%3}, [%4];" \
                 : "=r"((R)[0]), "=r"((R)[1]), "=r"((R)[2]), "=r"((R)[3])      \
                 : "r"(smem_u32(ptr)))

#define MMA16816(D, A, b0, b1)                                                 \
    asm volatile("mma.sync.aligned.m16n8k16.row.col.f32.bf16.bf16.f32 "        \
                 "{%0,%1,%2,%3}, {%4,%5,%6,%7}, {%8,%9}, {%0,%1,%2,%3};"       \
                 : "+f"((D)[0]), "+f"((D)[1]), "+f"((D)[2]), "+f"((D)[3])      \
                 : "r"((A)[0]), "r"((A)[1]), "r"((A)[2]), "r"((A)[3]),         \
                   "r"(b0), "r"(b1))

__device__ __forceinline__ void cp16(uint32_t dst, const void* src) {
    asm volatile("cp.async.cg.shared.global [%0], [%1], 16;" :: "r"(dst), "l"(src));
}
#define CP_COMMIT() asm volatile("cp.async.commit_group;")
#define CP_WAIT0()  asm volatile("cp.async.wait_group 0;")

__device__ __forceinline__ void split_bf16(float x, __nv_bfloat16& h, __nv_bfloat16& l) {
    h = __float2bfloat16(x);
    l = __float2bfloat16(x - __bfloat162float(h));
}

__device__ __forceinline__ uint32_t pack2(float a, float b) {
    __nv_bfloat162 t = __halves2bfloat162(__float2bfloat16(a), __float2bfloat16(b));
    return *reinterpret_cast<uint32_t*>(&t);
}

// ---------------------------------------------------------------------------
// Elementwise fp32 -> bf16 hi/lo split
// ---------------------------------------------------------------------------
__global__ __launch_bounds__(256) void split_pass(
    const float* __restrict__ in, __nv_bfloat16* __restrict__ oh,
    __nv_bfloat16* __restrict__ ol, int n4)
{
    int i = blockIdx.x * blockDim.x + threadIdx.x;
    if (i >= n4) return;
    float4 v = reinterpret_cast<const float4*>(in)[i];
    __nv_bfloat16 h0, l0, h1, l1, h2, l2, h3, l3;
    split_bf16(v.x, h0, l0); split_bf16(v.y, h1, l1);
    split_bf16(v.z, h2, l2); split_bf16(v.w, h3, l3);
    reinterpret_cast<__nv_bfloat162*>(oh)[2*i]   = __halves2bfloat162(h0, h1);
    reinterpret_cast<__nv_bfloat162*>(oh)[2*i+1] = __halves2bfloat162(h2, h3);
    reinterpret_cast<__nv_bfloat162*>(ol)[2*i]   = __halves2bfloat162(l0, l1);
    reinterpret_cast<__nv_bfloat162*>(ol)[2*i+1] = __halves2bfloat162(l2, l3);
}

// ---------------------------------------------------------------------------
// GEMM on pre-split bf16 hi/lo, cp.async 2-stage, BK=64 (16 iterations —
// halves per-iteration barrier/phase overhead). Block tile 128x64,
// 256 threads = 8 warps (4m x 2n), warp tile 32x32, 4 k16 steps per iter.
// MODE 0: A = g_x{h,l}, W = g_wqkv{h,l}; scatter into g_{q,k,v}{h,l}.
// MODE 1: A = g_y{h,l}, W = g_wp{h,l};  fp32 row-major output + bias.
// ---------------------------------------------------------------------------
template <int MODE>
__global__ __launch_bounds__(256, 2) void gemm_pre(
    const float* __restrict__ bias, float* __restrict__ Cout, int M, int N, int K)
{
    constexpr int LDA = 72;    // A smem stride (64+8), bf16
    constexpr int LDB = 72;    // B smem stride (64+8), bf16
    constexpr int ASZ = 128 * LDA;          // 9216 elems per A part
    constexpr int BSZ = 64 * LDB;           // 4608 elems per B part
    constexpr int STAGE = 2 * ASZ + 2 * BSZ; // 27648 elems = 55296 B

    extern __shared__ __nv_bfloat16 smem[];

    const __nv_bfloat16* Agh = (MODE == 0) ? g_xh : g_yh;
    const __nv_bfloat16* Agl = (MODE == 0) ? g_xl : g_yl;
    const __nv_bfloat16* Wgh = (MODE == 0) ? g_wqkvh : g_wph;
    const __nv_bfloat16* Wgl = (MODE == 0) ? g_wqkvl : g_wpl;

    int tid  = threadIdx.x;
    int lane = tid & 31, warp = tid >> 5;
    int cRow = blockIdx.y, cCol = blockIdx.x;
    int warpM = warp & 3, warpN = warp >> 2;      // 4m x 2n
    int mr0 = warpM * 32;
    int n0w = warpN * 32;

    const __nv_bfloat16* Abh = Agh + (size_t)cRow * 128 * K;
    const __nv_bfloat16* Abl = Agl + (size_t)cRow * 128 * K;
    const __nv_bfloat16* Wbh = Wgh + cCol * 64;
    const __nv_bfloat16* Wbl = Wgl + cCol * 64;

    uint32_t smem_base = smem_u32(smem);

    // copy coords: A tile 128x64 per part (1024 chunks of 8 bf16, 4 passes);
    //              B tile 64x64 per part (512 chunks, 2 passes)
    auto issue_stage = [&](int st, int k0) {
        uint32_t sb = smem_base + st * STAGE * 2;
        uint32_t ah = sb, al = sb + ASZ * 2, bh = sb + 2 * ASZ * 2, bl = sb + (2 * ASZ + BSZ) * 2;
        #pragma unroll
        for (int p = 0; p < 4; p++) {
            int id = tid + p * 256;
            int r = id >> 3, c8 = (id & 7) << 3;
            uint32_t so = (uint32_t)(r * LDA + c8) * 2;
            size_t go = (size_t)r * K + k0 + c8;
            cp16(ah + so, Abh + go);
            cp16(al + so, Abl + go);
        }
        #pragma unroll
        for (int p = 0; p < 2; p++) {
            int id = tid + p * 256;
            int r = id >> 3, c8 = (id & 7) << 3;
            uint32_t so = (uint32_t)(r * LDB + c8) * 2;
            size_t go = (size_t)(k0 + r) * N + c8;
            cp16(bh + so, Wbh + go);
            cp16(bl + so, Wbl + go);
        }
    };

    float acc[2][4][4];    // [mi][nj][frag] : warp tile 32x32
    #pragma unroll
    for (int i = 0; i < 2; i++)
        #pragma unroll
        for (int j = 0; j < 4; j++)
            #pragma unroll
            for (int q = 0; q < 4; q++) acc[i][j][q] = 0.f;

    issue_stage(0, 0);
    CP_COMMIT();

    int NT = K / 64;    // 16 iterations
    for (int it = 0; it < NT; it++) {
        CP_WAIT0();
        __syncthreads();
        if (it + 1 < NT) {
            issue_stage((it + 1) & 1, (it + 1) * 64);
            CP_COMMIT();
        }

        __nv_bfloat16* Ah = smem + (it & 1) * STAGE;
        __nv_bfloat16* Al = Ah + ASZ;
        __nv_bfloat16* Bh = Al + ASZ;
        __nv_bfloat16* Bl = Bh + BSZ;

        #pragma unroll
        for (int ks = 0; ks < 4; ks++) {
            int kk = ks * 16;
            uint32_t ahf[2][4], alf[2][4], bhf[2][4], blf[2][4];

            #pragma unroll
            for (int mi = 0; mi < 2; mi++) {
                int off = (mr0 + mi * 16 + (lane & 15)) * LDA + kk + ((lane >> 4) << 3);
                LDSM4(ahf[mi], &Ah[off]);
                LDSM4(alf[mi], &Al[off]);
            }
            #pragma unroll
            for (int g = 0; g < 2; g++) {
                int r = kk + ((lane & 16) >> 1) + (lane & 7);
                int c = n0w + g * 16 + (lane & 8);
                int off = r * LDB + c;
                LDSM4T(bhf[g], &Bh[off]);
                LDSM4T(blf[g], &Bl[off]);
            }

            #pragma unroll
            for (int mi = 0; mi < 2; mi++)
                #pragma unroll
                for (int nj = 0; nj < 4; nj++) {
                    int g = nj >> 1, h = nj & 1;
                    uint32_t b0h = h ? bhf[g][1] : bhf[g][0];
                    uint32_t b1h = h ? bhf[g][3] : bhf[g][2];
                    uint32_t b0l = h ? blf[g][1] : blf[g][0];
                    uint32_t b1l = h ? blf[g][3] : blf[g][2];
                    MMA16816(acc[mi][nj], ahf[mi], b0h, b1h);
                    MMA16816(acc[mi][nj], ahf[mi], b0l, b1l);
                    MMA16816(acc[mi][nj], alf[mi], b0h, b1h);
                }
        }
    }

    // --- epilogue ---
    int rbase = cRow * 128 + mr0 + (lane >> 2);
    int cbase = cCol * 64 + n0w + ((lane & 3) << 1);

    #pragma unroll
    for (int mi = 0; mi < 2; mi++) {
        #pragma unroll
        for (int nj = 0; nj < 4; nj++) {
            int m0 = rbase + mi * 16;
            int n  = cbase + nj * 8;
            float bv0 = bias[n], bv1 = bias[n + 1];
            float v00 = acc[mi][nj][0] + bv0, v01 = acc[mi][nj][1] + bv1;
            float v10 = acc[mi][nj][2] + bv0, v11 = acc[mi][nj][3] + bv1;
            if (MODE == 1) {
                *reinterpret_cast<float2*>(&Cout[(size_t)m0 * N + n])       = make_float2(v00, v01);
                *reinterpret_cast<float2*>(&Cout[(size_t)(m0 + 8) * N + n]) = make_float2(v10, v11);
            } else {
                int which = n / C_;
                int c = n - which * C_;
                int h = c >> 6, d = c & 63;
                __nv_bfloat16* dh = (which == 0) ? g_qh : (which == 1) ? g_kh : g_vh;
                __nv_bfloat16* dl = (which == 0) ? g_ql : (which == 1) ? g_kl : g_vl;
                int b0i = m0 >> 11, t0 = m0 & 2047;
                int b1i = (m0 + 8) >> 11, t1 = (m0 + 8) & 2047;
                size_t i0 = (((size_t)b0i * NH_ + h) * T_ + t0) * HD_ + d;
                size_t i1 = (((size_t)b1i * NH_ + h) * T_ + t1) * HD_ + d;
                __nv_bfloat16 h00, l00, h01, l01, h10, l10, h11, l11;
                split_bf16(v00, h00, l00); split_bf16(v01, h01, l01);
                split_bf16(v10, h10, l10); split_bf16(v11, h11, l11);
                *reinterpret_cast<__nv_bfloat162*>(&dh[i0]) = __halves2bfloat162(h00, h01);
                *reinterpret_cast<__nv_bfloat162*>(&dl[i0]) = __halves2bfloat162(l00, l01);
                *reinterpret_cast<__nv_bfloat162*>(&dh[i1]) = __halves2bfloat162(h10, h11);
                *reinterpret_cast<__nv_bfloat162*>(&dl[i1]) = __halves2bfloat162(l10, l11);
            }
        }
    }
}

// ---------------------------------------------------------------------------
// Flash attention via tensor cores, causal. CTA: 128 q-rows, 64-key iters.
// 8 warps x 16 rows. bf16x3. (unchanged — passing R12 version)
// ---------------------------------------------------------------------------
__global__ __launch_bounds__(256) void flash_mma_kernel()
{
    constexpr int LDS_ = 72;
    extern __shared__ __nv_bfloat16 smf[];
    __nv_bfloat16* Qh = smf;
    __nv_bfloat16* Ql = Qh + 128 * LDS_;
    __nv_bfloat16* Kh = Ql + 128 * LDS_;
    __nv_bfloat16* Kl = Kh + 64 * LDS_;
    __nv_bfloat16* Vh = Kl + 64 * LDS_;
    __nv_bfloat16* Vl = Vh + 64 * LDS_;

    int bh = blockIdx.y;
    int qt = gridDim.x - 1 - blockIdx.x;
    int q0 = qt * 128;
    int tid = threadIdx.x;
    int warp = tid >> 5, lane = tid & 31;
    int wrow = warp * 16;
    int g = lane >> 2, t2 = (lane & 3) << 1;

    const __nv_bfloat16* Qgh = g_qh + ((size_t)bh * T_ + q0) * HD_;
    const __nv_bfloat16* Qgl = g_ql + ((size_t)bh * T_ + q0) * HD_;

    #pragma unroll
    for (int i = 0; i < 4; i++) {
        int idx = (tid + i * 256) * 8;
        int r = idx >> 6, c = idx & 63;
        cp16(smem_u32(&Qh[r * LDS_ + c]), &Qgh[r * 64 + c]);
        cp16(smem_u32(&Ql[r * LDS_ + c]), &Qgl[r * 64 + c]);
    }
    CP_COMMIT();

    float O[8][4];
    #pragma unroll
    for (int i = 0; i < 8; i++)
        #pragma unroll
        for (int q = 0; q < 4; q++) O[i][q] = 0.f;
    float m0 = -INFINITY, m1 = -INFINITY, l0 = 0.f, l1 = 0.f;

    const float scale = 0.125f;
    int row0 = q0 + wrow + g;
    int row1 = row0 + 8;

    CP_WAIT0();
    __syncthreads();

    int kt_max = 2 * qt + 1;
    for (int kt = 0; kt <= kt_max; kt++) {
        int k0 = kt * 64;

        {
            const __nv_bfloat16* kgh = g_kh + ((size_t)bh * T_ + k0) * HD_;
            const __nv_bfloat16* kgl = g_kl + ((size_t)bh * T_ + k0) * HD_;
            const __nv_bfloat16* vgh = g_vh + ((size_t)bh * T_ + k0) * HD_;
            const __nv_bfloat16* vgl = g_vl + ((size_t)bh * T_ + k0) * HD_;
            #pragma unroll
            for (int i = 0; i < 2; i++) {
                int idx = (tid + i * 256) * 8;
                int r = idx >> 6, c = idx & 63;
                cp16(smem_u32(&Kh[r * LDS_ + c]), &kgh[r * 64 + c]);
                cp16(smem_u32(&Kl[r * LDS_ + c]), &kgl[r * 64 + c]);
                cp16(smem_u32(&Vh[r * LDS_ + c]), &vgh[r * 64 + c]);
                cp16(smem_u32(&Vl[r * LDS_ + c]), &vgl[r * 64 + c]);
            }
            CP_COMMIT();
            CP_WAIT0();
        }
        __syncthreads();

        float S[8][4];
        #pragma unroll
        for (int j = 0; j < 8; j++)
            #pragma unroll
            for (int q = 0; q < 4; q++) S[j][q] = 0.f;

        #pragma unroll
        for (int ks = 0; ks < 4; ks++) {
            int kk = ks * 16;
            uint32_t qhf[4], qlf[4];
            {
                int off = (wrow + (lane & 15)) * LDS_ + kk + ((lane >> 4) << 3);
                LDSM4(qhf, &Qh[off]);
                LDSM4(qlf, &Ql[off]);
            }
            uint32_t bKh[8][2], bKl[8][2];
            #pragma unroll
            for (int tp = 0; tp < 4; tp++) {
                uint32_t R[4];
                int off = (tp * 16 + (lane & 7) + ((lane >> 4) << 3)) * LDS_
                          + kk + (((lane >> 3) & 1) << 3);
                LDSM4(R, &Kh[off]);
                bKh[2*tp][0] = R[0]; bKh[2*tp][1] = R[1];
                bKh[2*tp+1][0] = R[2]; bKh[2*tp+1][1] = R[3];
                LDSM4(R, &Kl[off]);
                bKl[2*tp][0] = R[0]; bKl[2*tp][1] = R[1];
                bKl[2*tp+1][0] = R[2]; bKl[2*tp+1][1] = R[3];
            }
            #pragma unroll
            for (int j = 0; j < 8; j++) {
                MMA16816(S[j], qhf, bKh[j][0], bKh[j][1]);
                MMA16816(S[j], qlf, bKh[j][0], bKh[j][1]);
                MMA16816(S[j], qhf, bKl[j][0], bKl[j][1]);
            }
        }

        if (kt >= 2 * qt) {
            #pragma unroll
            for (int j = 0; j < 8; j++) {
                int key = k0 + j * 8 + t2;
                if (key     > row0) S[j][0] = -1e30f;
                if (key + 1 > row0) S[j][1] = -1e30f;
                if (key     > row1) S[j][2] = -1e30f;
                if (key + 1 > row1) S[j][3] = -1e30f;
            }
        }

        float mx0 = -1e30f, mx1 = -1e30f;
        #pragma unroll
        for (int j = 0; j < 8; j++) {
            mx0 = fmaxf(mx0, fmaxf(S[j][0], S[j][1]));
            mx1 = fmaxf(mx1, fmaxf(S[j][2], S[j][3]));
        }
        #pragma unroll
        for (int off = 1; off <= 2; off <<= 1) {
            mx0 = fmaxf(mx0, __shfl_xor_sync(0xffffffffu, mx0, off));
            mx1 = fmaxf(mx1, __shfl_xor_sync(0xffffffffu, mx1, off));
        }
        float mn0 = fmaxf(m0, mx0 * scale);
        float mn1 = fmaxf(m1, mx1 * scale);
        float a0 = __expf(m0 - mn0);
        float a1 = __expf(m1 - mn1);
        m0 = mn0; m1 = mn1;

        float s0 = 0.f, s1 = 0.f;
        #pragma unroll
        for (int j = 0; j < 8; j++) {
            S[j][0] = __expf(fmaf(S[j][0], scale, -mn0));
            S[j][1] = __expf(fmaf(S[j][1], scale, -mn0));
            S[j][2] = __expf(fmaf(S[j][2], scale, -mn1));
            S[j][3] = __expf(fmaf(S[j][3], scale, -mn1));
            s0 += S[j][0] + S[j][1];
            s1 += S[j][2] + S[j][3];
        }
        #pragma unroll
        for (int off = 1; off <= 2; off <<= 1) {
            s0 += __shfl_xor_sync(0xffffffffu, s0, off);
            s1 += __shfl_xor_sync(0xffffffffu, s1, off);
        }
        l0 = l0 * a0 + s0;
        l1 = l1 * a1 + s1;
        #pragma unroll
        for (int i = 0; i < 8; i++) {
            O[i][0] *= a0; O[i][1] *= a0;
            O[i][2] *= a1; O[i][3] *= a1;
        }

        #pragma unroll
        for (int ks = 0; ks < 4; ks++) {
            int j0 = 2 * ks, j1 = 2 * ks + 1;
            uint32_t aPh[4], aPl[4];
            aPh[0] = pack2(S[j0][0], S[j0][1]);
            aPh[1] = pack2(S[j0][2], S[j0][3]);
            aPh[2] = pack2(S[j1][0], S[j1][1]);
            aPh[3] = pack2(S[j1][2], S[j1][3]);
            {
                __nv_bfloat162 h;
                h = *reinterpret_cast<__nv_bfloat162*>(&aPh[0]);
                aPl[0] = pack2(S[j0][0] - __low2float(h), S[j0][1] - __high2float(h));
                h = *reinterpret_cast<__nv_bfloat162*>(&aPh[1]);
                aPl[1] = pack2(S[j0][2] - __low2float(h), S[j0][3] - __high2float(h));
                h = *reinterpret_cast<__nv_bfloat162*>(&aPh[2]);
                aPl[2] = pack2(S[j1][0] - __low2float(h), S[j1][1] - __high2float(h));
                h = *reinterpret_cast<__nv_bfloat162*>(&aPh[3]);
                aPl[3] = pack2(S[j1][2] - __low2float(h), S[j1][3] - __high2float(h));
            }
            uint32_t Rh[4][4], Rl[4][4];
            #pragma unroll
            for (int gd = 0; gd < 4; gd++) {
                int off = (ks * 16 + ((lane & 16) >> 1) + (lane & 7)) * LDS_
                          + gd * 16 + (lane & 8);
                LDSM4T(Rh[gd], &Vh[off]);
                LDSM4T(Rl[gd], &Vl[off]);
            }
            #pragma unroll
            for (int gd = 0; gd < 4; gd++) {
                MMA16816(O[gd*2+0], aPh, Rh[gd][0], Rh[gd][2]);
                MMA16816(O[gd*2+1], aPh, Rh[gd][1], Rh[gd][3]);
                MMA16816(O[gd*2+0], aPl, Rh[gd][0], Rh[gd][2]);
                MMA16816(O[gd*2+1], aPl, Rh[gd][1], Rh[gd][3]);
                MMA16816(O[gd*2+0], aPh, Rl[gd][0], Rl[gd][2]);
                MMA16816(O[gd*2+1], aPh, Rl[gd][1], Rl[gd][3]);
            }
        }
        __syncthreads();
    }

    int b = bh >> 4, h = bh & 15;
    float inv0 = 1.f / l0, inv1 = 1.f / l1;
    size_t base0 = ((size_t)b * T_ + row0) * C_ + h * 64 + t2;
    size_t base1 = ((size_t)b * T_ + row1) * C_ + h * 64 + t2;
    #pragma unroll
    for (int i = 0; i < 8; i++) {
        float v0 = O[i][0] * inv0, v1 = O[i][1] * inv0;
        float v2 = O[i][2] * inv1, v3 = O[i][3] * inv1;
        __nv_bfloat16 h0, l0b, h1, l1b, h2, l2b, h3, l3b;
        split_bf16(v0, h0, l0b); split_bf16(v1, h1, l1b);
        split_bf16(v2, h2, l2b); split_bf16(v3, h3, l3b);
        *reinterpret_cast<__nv_bfloat162*>(&g_yh[base0 + i * 8]) = __halves2bfloat162(h0, h1);
        *reinterpret_cast<__nv_bfloat162*>(&g_yl[base0 + i * 8]) = __halves2bfloat162(l0b, l1b);
        *reinterpret_cast<__nv_bfloat162*>(&g_yh[base1 + i * 8]) = __halves2bfloat162(h2, h3);
        *reinterpret_cast<__nv_bfloat162*>(&g_yl[base1 + i * 8]) = __halves2bfloat162(l2b, l3b);
    }
}

// ---------------------------------------------------------------------------
extern "C" void kernel_launch(void* const* d_in, const int* in_sizes, int n_in,
                              void* d_out, int out_size)
{
    const float* x     = (const float*)d_in[0];
    const float* Wqkv  = (const float*)d_in[1];
    const float* bqkv  = (const float*)d_in[2];
    const float* Wproj = (const float*)d_in[3];
    const float* bproj = (const float*)d_in[4];
    float* out = (float*)d_out;

    static __nv_bfloat16 *xh_p = nullptr, *xl_p, *wqh_p, *wql_p, *wph_p, *wpl_p;
    if (!xh_p) {
        cudaGetSymbolAddress((void**)&xh_p,  g_xh);
        cudaGetSymbolAddress((void**)&xl_p,  g_xl);
        cudaGetSymbolAddress((void**)&wqh_p, g_wqkvh);
        cudaGetSymbolAddress((void**)&wql_p, g_wqkvl);
        cudaGetSymbolAddress((void**)&wph_p, g_wph);
        cudaGetSymbolAddress((void**)&wpl_p, g_wpl);
    }

    // 0) Pre-split fp32 inputs into bf16 hi/lo
    split_pass<<<(M_ * C_ / 4 + 255) / 256, 256>>>(x, xh_p, xl_p, M_ * C_ / 4);
    split_pass<<<(C_ * 3 * C_ / 4 + 255) / 256, 256>>>(Wqkv, wqh_p, wql_p, C_ * 3 * C_ / 4);
    split_pass<<<(C_ * C_ / 4 + 255) / 256, 256>>>(Wproj, wph_p, wpl_p, C_ * C_ / 4);

    const int gemm_smem = 2 * (2 * 128 * 72 + 2 * 64 * 72) * (int)sizeof(__nv_bfloat16); // 110592

    // 1) QKV GEMM -> bf16 hi/lo Q,K,V
    {
        cudaFuncSetAttribute(gemm_pre<0>, cudaFuncAttributeMaxDynamicSharedMemorySize, gemm_smem);
        dim3 grid(3072 / 64, 8192 / 128);
        gemm_pre<0><<<grid, 256, gemm_smem>>>(bqkv, nullptr, M_, 3 * C_, C_);
    }

    // 2) Flash attention (tensor cores), writes g_yh/g_yl
    {
        const int smem = (2 * 128 * 72 + 4 * 64 * 72) * (int)sizeof(__nv_bfloat16); // 73728
        cudaFuncSetAttribute(flash_mma_kernel, cudaFuncAttributeMaxDynamicSharedMemorySize, smem);
        flash_mma_kernel<<<dim3(16, 64), 256, smem>>>();
    }

    // 3) Projection GEMM: y @ Wproj + bproj -> out
    {
        cudaFuncSetAttribute(gemm_pre<1>, cudaFuncAttributeMaxDynamicSharedMemorySize, gemm_smem);
        dim3 grid(1024 / 64, 8192 / 128);
        gemm_pre<1><<<grid, 256, gemm_smem>>>(bproj, out, M_, C_, C_);
    }
}

// round 14
// speedup vs baseline: 1.1541x; 1.0237x over previous
#include <cuda_runtime.h>
#include <cuda_bf16.h>
#include <math.h>
#include <stdint.h>

// Problem constants
#define B_  4
#define T_  2048
#define C_  1024
#define NH_ 16
#define HD_ 64
#define BH_ (B_*NH_)     // 64
#define M_  (B_*T_)      // 8192

// Scratch (allocation-free device globals), all bf16 hi/lo split pairs
__device__ __nv_bfloat16 g_xh[M_*C_],      g_xl[M_*C_];        // x split
__device__ __nv_bfloat16 g_wqkvh[C_*3*C_], g_wqkvl[C_*3*C_];   // Wqkv split [K][N]
__device__ __nv_bfloat16 g_wph[C_*C_],     g_wpl[C_*C_];       // Wproj split [K][N]
__device__ __nv_bfloat16 g_qh[BH_*T_*HD_], g_ql[BH_*T_*HD_];   // [B,NH,T,HD]
__device__ __nv_bfloat16 g_kh[BH_*T_*HD_], g_kl[BH_*T_*HD_];
__device__ __nv_bfloat16 g_vh[BH_*T_*HD_], g_vl[BH_*T_*HD_];
__device__ __nv_bfloat16 g_yh[M_*C_],      g_yl[M_*C_];        // attention out split

__device__ __forceinline__ uint32_t smem_u32(const void* p) {
    return (uint32_t)__cvta_generic_to_shared(p);
}

#define LDSM4(R, ptr)                                                          \
    asm volatile("ldmatrix.sync.aligned.m8n8.x4.shared.b16 {%0,%1,%2,%3}, [%4];" \
                 : "=r"((R)[0]), "=r"((R)[1]), "=r"((R)[2]), "=r"((R)[3])      \
                 : "r"(smem_u32(ptr)))

#define LDSM4T(R, ptr)                                                         \
    asm volatile("ldmatrix.sync.aligned.m8n8.x4.trans.shared.b16 {%0,%1,%2,%3}, [%4];" \
                 : "=r"((R)[0]), "=r"((R)[1]), "=r"((R)[2]), "=r"((R)[3])      \
                 : "r"(smem_u32(ptr)))

#define MMA16816(D, A, b0, b1)                                                 \
    asm volatile("mma.sync.aligned.m16n8k16.row.col.f32.bf16.bf16.f32 "        \
                 "{%0,%1,%2,%3}, {%4,%5,%6,%7}, {%8,%9}, {%0,%1,%2,%3};"       \
                 : "+f"((D)[0]), "+f"((D)[1]), "+f"((D)[2]), "+f"((D)[3])      \
                 : "r"((A)[0]), "r"((A)[1]), "r"((A)[2]), "r"((A)[3]),         \
                   "r"(b0), "r"(b1))

__device__ __forceinline__ void cp16(uint32_t dst, const void* src) {
    asm volatile("cp.async.cg.shared.global [%0], [%1], 16;" :: "r"(dst), "l"(src));
}
#define CP_COMMIT() asm volatile("cp.async.commit_group;")
#define CP_WAIT0()  asm volatile("cp.async.wait_group 0;")
#define CP_WAIT1()  asm volatile("cp.async.wait_group 1;")

__device__ __forceinline__ void split_bf16(float x, __nv_bfloat16& h, __nv_bfloat16& l) {
    h = __float2bfloat16(x);
    l = __float2bfloat16(x - __bfloat162float(h));
}

__device__ __forceinline__ uint32_t pack2(float a, float b) {
    __nv_bfloat162 t = __halves2bfloat162(__float2bfloat16(a), __float2bfloat16(b));
    return *reinterpret_cast<uint32_t*>(&t);
}

// ---------------------------------------------------------------------------
// Elementwise fp32 -> bf16 hi/lo split
// ---------------------------------------------------------------------------
__global__ __launch_bounds__(256) void split_pass(
    const float* __restrict__ in, __nv_bfloat16* __restrict__ oh,
    __nv_bfloat16* __restrict__ ol, int n4)
{
    int i = blockIdx.x * blockDim.x + threadIdx.x;
    if (i >= n4) return;
    float4 v = reinterpret_cast<const float4*>(in)[i];
    __nv_bfloat16 h0, l0, h1, l1, h2, l2, h3, l3;
    split_bf16(v.x, h0, l0); split_bf16(v.y, h1, l1);
    split_bf16(v.z, h2, l2); split_bf16(v.w, h3, l3);
    reinterpret_cast<__nv_bfloat162*>(oh)[2*i]   = __halves2bfloat162(h0, h1);
    reinterpret_cast<__nv_bfloat162*>(oh)[2*i+1] = __halves2bfloat162(h2, h3);
    reinterpret_cast<__nv_bfloat162*>(ol)[2*i]   = __halves2bfloat162(l0, l1);
    reinterpret_cast<__nv_bfloat162*>(ol)[2*i+1] = __halves2bfloat162(l2, l3);
}

// ---------------------------------------------------------------------------
// GEMM on pre-split bf16 hi/lo, cp.async 2-stage, BK=64. (R13, passing)
// ---------------------------------------------------------------------------
template <int MODE>
__global__ __launch_bounds__(256, 2) void gemm_pre(
    const float* __restrict__ bias, float* __restrict__ Cout, int M, int N, int K)
{
    constexpr int LDA = 72;
    constexpr int LDB = 72;
    constexpr int ASZ = 128 * LDA;
    constexpr int BSZ = 64 * LDB;
    constexpr int STAGE = 2 * ASZ + 2 * BSZ;

    extern __shared__ __nv_bfloat16 smem[];

    const __nv_bfloat16* Agh = (MODE == 0) ? g_xh : g_yh;
    const __nv_bfloat16* Agl = (MODE == 0) ? g_xl : g_yl;
    const __nv_bfloat16* Wgh = (MODE == 0) ? g_wqkvh : g_wph;
    const __nv_bfloat16* Wgl = (MODE == 0) ? g_wqkvl : g_wpl;

    int tid  = threadIdx.x;
    int lane = tid & 31, warp = tid >> 5;
    int cRow = blockIdx.y, cCol = blockIdx.x;
    int warpM = warp & 3, warpN = warp >> 2;
    int mr0 = warpM * 32;
    int n0w = warpN * 32;

    const __nv_bfloat16* Abh = Agh + (size_t)cRow * 128 * K;
    const __nv_bfloat16* Abl = Agl + (size_t)cRow * 128 * K;
    const __nv_bfloat16* Wbh = Wgh + cCol * 64;
    const __nv_bfloat16* Wbl = Wgl + cCol * 64;

    uint32_t smem_base = smem_u32(smem);

    auto issue_stage = [&](int st, int k0) {
        uint32_t sb = smem_base + st * STAGE * 2;
        uint32_t ah = sb, al = sb + ASZ * 2, bh = sb + 2 * ASZ * 2, bl = sb + (2 * ASZ + BSZ) * 2;
        #pragma unroll
        for (int p = 0; p < 4; p++) {
            int id = tid + p * 256;
            int r = id >> 3, c8 = (id & 7) << 3;
            uint32_t so = (uint32_t)(r * LDA + c8) * 2;
            size_t go = (size_t)r * K + k0 + c8;
            cp16(ah + so, Abh + go);
            cp16(al + so, Abl + go);
        }
        #pragma unroll
        for (int p = 0; p < 2; p++) {
            int id = tid + p * 256;
            int r = id >> 3, c8 = (id & 7) << 3;
            uint32_t so = (uint32_t)(r * LDB + c8) * 2;
            size_t go = (size_t)(k0 + r) * N + c8;
            cp16(bh + so, Wbh + go);
            cp16(bl + so, Wbl + go);
        }
    };

    float acc[2][4][4];
    #pragma unroll
    for (int i = 0; i < 2; i++)
        #pragma unroll
        for (int j = 0; j < 4; j++)
            #pragma unroll
            for (int q = 0; q < 4; q++) acc[i][j][q] = 0.f;

    issue_stage(0, 0);
    CP_COMMIT();

    int NT = K / 64;
    for (int it = 0; it < NT; it++) {
        CP_WAIT0();
        __syncthreads();
        if (it + 1 < NT) {
            issue_stage((it + 1) & 1, (it + 1) * 64);
            CP_COMMIT();
        }

        __nv_bfloat16* Ah = smem + (it & 1) * STAGE;
        __nv_bfloat16* Al = Ah + ASZ;
        __nv_bfloat16* Bh = Al + ASZ;
        __nv_bfloat16* Bl = Bh + BSZ;

        #pragma unroll
        for (int ks = 0; ks < 4; ks++) {
            int kk = ks * 16;
            uint32_t ahf[2][4], alf[2][4], bhf[2][4], blf[2][4];

            #pragma unroll
            for (int mi = 0; mi < 2; mi++) {
                int off = (mr0 + mi * 16 + (lane & 15)) * LDA + kk + ((lane >> 4) << 3);
                LDSM4(ahf[mi], &Ah[off]);
                LDSM4(alf[mi], &Al[off]);
            }
            #pragma unroll
            for (int g = 0; g < 2; g++) {
                int r = kk + ((lane & 16) >> 1) + (lane & 7);
                int c = n0w + g * 16 + (lane & 8);
                int off = r * LDB + c;
                LDSM4T(bhf[g], &Bh[off]);
                LDSM4T(blf[g], &Bl[off]);
            }

            #pragma unroll
            for (int mi = 0; mi < 2; mi++)
                #pragma unroll
                for (int nj = 0; nj < 4; nj++) {
                    int g = nj >> 1, h = nj & 1;
                    uint32_t b0h = h ? bhf[g][1] : bhf[g][0];
                    uint32_t b1h = h ? bhf[g][3] : bhf[g][2];
                    uint32_t b0l = h ? blf[g][1] : blf[g][0];
                    uint32_t b1l = h ? blf[g][3] : blf[g][2];
                    MMA16816(acc[mi][nj], ahf[mi], b0h, b1h);
                    MMA16816(acc[mi][nj], ahf[mi], b0l, b1l);
                    MMA16816(acc[mi][nj], alf[mi], b0h, b1h);
                }
        }
    }

    // --- epilogue ---
    int rbase = cRow * 128 + mr0 + (lane >> 2);
    int cbase = cCol * 64 + n0w + ((lane & 3) << 1);

    #pragma unroll
    for (int mi = 0; mi < 2; mi++) {
        #pragma unroll
        for (int nj = 0; nj < 4; nj++) {
            int m0 = rbase + mi * 16;
            int n  = cbase + nj * 8;
            float bv0 = bias[n], bv1 = bias[n + 1];
            float v00 = acc[mi][nj][0] + bv0, v01 = acc[mi][nj][1] + bv1;
            float v10 = acc[mi][nj][2] + bv0, v11 = acc[mi][nj][3] + bv1;
            if (MODE == 1) {
                *reinterpret_cast<float2*>(&Cout[(size_t)m0 * N + n])       = make_float2(v00, v01);
                *reinterpret_cast<float2*>(&Cout[(size_t)(m0 + 8) * N + n]) = make_float2(v10, v11);
            } else {
                int which = n / C_;
                int c = n - which * C_;
                int h = c >> 6, d = c & 63;
                __nv_bfloat16* dh = (which == 0) ? g_qh : (which == 1) ? g_kh : g_vh;
                __nv_bfloat16* dl = (which == 0) ? g_ql : (which == 1) ? g_kl : g_vl;
                int b0i = m0 >> 11, t0 = m0 & 2047;
                int b1i = (m0 + 8) >> 11, t1 = (m0 + 8) & 2047;
                size_t i0 = (((size_t)b0i * NH_ + h) * T_ + t0) * HD_ + d;
                size_t i1 = (((size_t)b1i * NH_ + h) * T_ + t1) * HD_ + d;
                __nv_bfloat16 h00, l00, h01, l01, h10, l10, h11, l11;
                split_bf16(v00, h00, l00); split_bf16(v01, h01, l01);
                split_bf16(v10, h10, l10); split_bf16(v11, h11, l11);
                *reinterpret_cast<__nv_bfloat162*>(&dh[i0]) = __halves2bfloat162(h00, h01);
                *reinterpret_cast<__nv_bfloat162*>(&dl[i0]) = __halves2bfloat162(l00, l01);
                *reinterpret_cast<__nv_bfloat162*>(&dh[i1]) = __halves2bfloat162(h10, h11);
                *reinterpret_cast<__nv_bfloat162*>(&dl[i1]) = __halves2bfloat162(l10, l11);
            }
        }
    }
}

// ---------------------------------------------------------------------------
// Flash attention, bf16x3, causal. 2-stage cp.async K/V pipeline +
// warp-level skip of fully-masked warps on the final diagonal tile.
// smem: Q hi/lo [128][72] + 2 stages x (Kh,Kl,Vh,Vl)[64][72] = 110592 B.
// ---------------------------------------------------------------------------
__global__ __launch_bounds__(256) void flash_mma_kernel()
{
    constexpr int LDS_ = 72;
    constexpr int KVPART = 64 * LDS_;         // one K or V part
    constexpr int KVSTAGE = 4 * KVPART;       // Kh,Kl,Vh,Vl per stage
    extern __shared__ __nv_bfloat16 smf[];
    __nv_bfloat16* Qh  = smf;                 // [128][72]
    __nv_bfloat16* Ql  = Qh + 128 * LDS_;
    __nv_bfloat16* KV  = Ql + 128 * LDS_;     // 2 stages

    int bh = blockIdx.y;
    int qt = gridDim.x - 1 - blockIdx.x;
    int q0 = qt * 128;
    int tid = threadIdx.x;
    int warp = tid >> 5, lane = tid & 31;
    int wrow = warp * 16;
    int g = lane >> 2, t2 = (lane & 3) << 1;

    const __nv_bfloat16* Qgh = g_qh + ((size_t)bh * T_ + q0) * HD_;
    const __nv_bfloat16* Qgl = g_ql + ((size_t)bh * T_ + q0) * HD_;

    // group A: Q tiles
    #pragma unroll
    for (int i = 0; i < 4; i++) {
        int idx = (tid + i * 256) * 8;
        int r = idx >> 6, c = idx & 63;
        cp16(smem_u32(&Qh[r * LDS_ + c]), &Qgh[r * 64 + c]);
        cp16(smem_u32(&Ql[r * LDS_ + c]), &Qgl[r * 64 + c]);
    }
    CP_COMMIT();

    auto issue_kv = [&](int st, int k0) {
        __nv_bfloat16* Kh = KV + st * KVSTAGE;
        __nv_bfloat16* Kl = Kh + KVPART;
        __nv_bfloat16* Vh = Kl + KVPART;
        __nv_bfloat16* Vl = Vh + KVPART;
        const __nv_bfloat16* kgh = g_kh + ((size_t)bh * T_ + k0) * HD_;
        const __nv_bfloat16* kgl = g_kl + ((size_t)bh * T_ + k0) * HD_;
        const __nv_bfloat16* vgh = g_vh + ((size_t)bh * T_ + k0) * HD_;
        const __nv_bfloat16* vgl = g_vl + ((size_t)bh * T_ + k0) * HD_;
        #pragma unroll
        for (int i = 0; i < 2; i++) {
            int idx = (tid + i * 256) * 8;
            int r = idx >> 6, c = idx & 63;
            cp16(smem_u32(&Kh[r * LDS_ + c]), &kgh[r * 64 + c]);
            cp16(smem_u32(&Kl[r * LDS_ + c]), &kgl[r * 64 + c]);
            cp16(smem_u32(&Vh[r * LDS_ + c]), &vgh[r * 64 + c]);
            cp16(smem_u32(&Vl[r * LDS_ + c]), &vgl[r * 64 + c]);
        }
    };

    // group B: KV stage 0
    issue_kv(0, 0);
    CP_COMMIT();

    float O[8][4];
    #pragma unroll
    for (int i = 0; i < 8; i++)
        #pragma unroll
        for (int q = 0; q < 4; q++) O[i][q] = 0.f;
    float m0 = -INFINITY, m1 = -INFINITY, l0 = 0.f, l1 = 0.f;

    const float scale = 0.125f;
    int row0 = q0 + wrow + g;
    int row1 = row0 + 8;

    int kt_max = 2 * qt + 1;
    for (int kt = 0; kt <= kt_max; kt++) {
        int k0 = kt * 64;

        if (kt + 1 <= kt_max) {
            issue_kv((kt + 1) & 1, (kt + 1) * 64);
            CP_COMMIT();
            CP_WAIT1();          // stage kt (and Q) complete; kt+1 in flight
        } else {
            CP_WAIT0();
        }
        __syncthreads();

        __nv_bfloat16* Kh = KV + (kt & 1) * KVSTAGE;
        __nv_bfloat16* Kl = Kh + KVPART;
        __nv_bfloat16* Vh = Kl + KVPART;
        __nv_bfloat16* Vl = Vh + KVPART;

        // Final diagonal tile: warps whose rows are all < k0 are fully masked.
        bool active = !(kt == kt_max && wrow < 64);

        if (active) {
            float S[8][4];
            #pragma unroll
            for (int j = 0; j < 8; j++)
                #pragma unroll
                for (int q = 0; q < 4; q++) S[j][q] = 0.f;

            #pragma unroll
            for (int ks = 0; ks < 4; ks++) {
                int kk = ks * 16;
                uint32_t qhf[4], qlf[4];
                {
                    int off = (wrow + (lane & 15)) * LDS_ + kk + ((lane >> 4) << 3);
                    LDSM4(qhf, &Qh[off]);
                    LDSM4(qlf, &Ql[off]);
                }
                uint32_t bKh[8][2], bKl[8][2];
                #pragma unroll
                for (int tp = 0; tp < 4; tp++) {
                    uint32_t R[4];
                    int off = (tp * 16 + (lane & 7) + ((lane >> 4) << 3)) * LDS_
                              + kk + (((lane >> 3) & 1) << 3);
                    LDSM4(R, &Kh[off]);
                    bKh[2*tp][0] = R[0]; bKh[2*tp][1] = R[1];
                    bKh[2*tp+1][0] = R[2]; bKh[2*tp+1][1] = R[3];
                    LDSM4(R, &Kl[off]);
                    bKl[2*tp][0] = R[0]; bKl[2*tp][1] = R[1];
                    bKl[2*tp+1][0] = R[2]; bKl[2*tp+1][1] = R[3];
                }
                #pragma unroll
                for (int j = 0; j < 8; j++) {
                    MMA16816(S[j], qhf, bKh[j][0], bKh[j][1]);
                    MMA16816(S[j], qlf, bKh[j][0], bKh[j][1]);
                    MMA16816(S[j], qhf, bKl[j][0], bKl[j][1]);
                }
            }

            if (kt >= 2 * qt) {
                #pragma unroll
                for (int j = 0; j < 8; j++) {
                    int key = k0 + j * 8 + t2;
                    if (key     > row0) S[j][0] = -1e30f;
                    if (key + 1 > row0) S[j][1] = -1e30f;
                    if (key     > row1) S[j][2] = -1e30f;
                    if (key + 1 > row1) S[j][3] = -1e30f;
                }
            }

            float mx0 = -1e30f, mx1 = -1e30f;
            #pragma unroll
            for (int j = 0; j < 8; j++) {
                mx0 = fmaxf(mx0, fmaxf(S[j][0], S[j][1]));
                mx1 = fmaxf(mx1, fmaxf(S[j][2], S[j][3]));
            }
            #pragma unroll
            for (int off = 1; off <= 2; off <<= 1) {
                mx0 = fmaxf(mx0, __shfl_xor_sync(0xffffffffu, mx0, off));
                mx1 = fmaxf(mx1, __shfl_xor_sync(0xffffffffu, mx1, off));
            }
            float mn0 = fmaxf(m0, mx0 * scale);
            float mn1 = fmaxf(m1, mx1 * scale);
            float a0 = __expf(m0 - mn0);
            float a1 = __expf(m1 - mn1);
            m0 = mn0; m1 = mn1;

            float s0 = 0.f, s1 = 0.f;
            #pragma unroll
            for (int j = 0; j < 8; j++) {
                S[j][0] = __expf(fmaf(S[j][0], scale, -mn0));
                S[j][1] = __expf(fmaf(S[j][1], scale, -mn0));
                S[j][2] = __expf(fmaf(S[j][2], scale, -mn1));
                S[j][3] = __expf(fmaf(S[j][3], scale, -mn1));
                s0 += S[j][0] + S[j][1];
                s1 += S[j][2] + S[j][3];
            }
            #pragma unroll
            for (int off = 1; off <= 2; off <<= 1) {
                s0 += __shfl_xor_sync(0xffffffffu, s0, off);
                s1 += __shfl_xor_sync(0xffffffffu, s1, off);
            }
            l0 = l0 * a0 + s0;
            l1 = l1 * a1 + s1;
            #pragma unroll
            for (int i = 0; i < 8; i++) {
                O[i][0] *= a0; O[i][1] *= a0;
                O[i][2] *= a1; O[i][3] *= a1;
            }

            #pragma unroll
            for (int ks = 0; ks < 4; ks++) {
                int j0 = 2 * ks, j1 = 2 * ks + 1;
                uint32_t aPh[4], aPl[4];
                aPh[0] = pack2(S[j0][0], S[j0][1]);
                aPh[1] = pack2(S[j0][2], S[j0][3]);
                aPh[2] = pack2(S[j1][0], S[j1][1]);
                aPh[3] = pack2(S[j1][2], S[j1][3]);
                {
                    __nv_bfloat162 h;
                    h = *reinterpret_cast<__nv_bfloat162*>(&aPh[0]);
                    aPl[0] = pack2(S[j0][0] - __low2float(h), S[j0][1] - __high2float(h));
                    h = *reinterpret_cast<__nv_bfloat162*>(&aPh[1]);
                    aPl[1] = pack2(S[j0][2] - __low2float(h), S[j0][3] - __high2float(h));
                    h = *reinterpret_cast<__nv_bfloat162*>(&aPh[2]);
                    aPl[2] = pack2(S[j1][0] - __low2float(h), S[j1][1] - __high2float(h));
                    h = *reinterpret_cast<__nv_bfloat162*>(&aPh[3]);
                    aPl[3] = pack2(S[j1][2] - __low2float(h), S[j1][3] - __high2float(h));
                }
                uint32_t Rh[4][4], Rl[4][4];
                #pragma unroll
                for (int gd = 0; gd < 4; gd++) {
                    int off = (ks * 16 + ((lane & 16) >> 1) + (lane & 7)) * LDS_
                              + gd * 16 + (lane & 8);
                    LDSM4T(Rh[gd], &Vh[off]);
                    LDSM4T(Rl[gd], &Vl[off]);
                }
                #pragma unroll
                for (int gd = 0; gd < 4; gd++) {
                    MMA16816(O[gd*2+0], aPh, Rh[gd][0], Rh[gd][2]);
                    MMA16816(O[gd*2+1], aPh, Rh[gd][1], Rh[gd][3]);
                    MMA16816(O[gd*2+0], aPl, Rh[gd][0], Rh[gd][2]);
                    MMA16816(O[gd*2+1], aPl, Rh[gd][1], Rh[gd][3]);
                    MMA16816(O[gd*2+0], aPh, Rl[gd][0], Rl[gd][2]);
                    MMA16816(O[gd*2+1], aPh, Rl[gd][1], Rl[gd][3]);
                }
            }
        }
        __syncthreads();   // all warps done with stage kt before it is refilled
    }

    int b = bh >> 4, h = bh & 15;
    float inv0 = 1.f / l0, inv1 = 1.f / l1;
    size_t base0 = ((size_t)b * T_ + row0) * C_ + h * 64 + t2;
    size_t base1 = ((size_t)b * T_ + row1) * C_ + h * 64 + t2;
    #pragma unroll
    for (int i = 0; i < 8; i++) {
        float v0 = O[i][0] * inv0, v1 = O[i][1] * inv0;
        float v2 = O[i][2] * inv1, v3 = O[i][3] * inv1;
        __nv_bfloat16 h0, l0b, h1, l1b, h2, l2b, h3, l3b;
        split_bf16(v0, h0, l0b); split_bf16(v1, h1, l1b);
        split_bf16(v2, h2, l2b); split_bf16(v3, h3, l3b);
        *reinterpret_cast<__nv_bfloat162*>(&g_yh[base0 + i * 8]) = __halves2bfloat162(h0, h1);
        *reinterpret_cast<__nv_bfloat162*>(&g_yl[base0 + i * 8]) = __halves2bfloat162(l0b, l1b);
        *reinterpret_cast<__nv_bfloat162*>(&g_yh[base1 + i * 8]) = __halves2bfloat162(h2, h3);
        *reinterpret_cast<__nv_bfloat162*>(&g_yl[base1 + i * 8]) = __halves2bfloat162(l2b, l3b);
    }
}

// ---------------------------------------------------------------------------
extern "C" void kernel_launch(void* const* d_in, const int* in_sizes, int n_in,
                              void* d_out, int out_size)
{
    const float* x     = (const float*)d_in[0];
    const float* Wqkv  = (const float*)d_in[1];
    const float* bqkv  = (const float*)d_in[2];
    const float* Wproj = (const float*)d_in[3];
    const float* bproj = (const float*)d_in[4];
    float* out = (float*)d_out;

    static __nv_bfloat16 *xh_p = nullptr, *xl_p, *wqh_p, *wql_p, *wph_p, *wpl_p;
    if (!xh_p) {
        cudaGetSymbolAddress((void**)&xh_p,  g_xh);
        cudaGetSymbolAddress((void**)&xl_p,  g_xl);
        cudaGetSymbolAddress((void**)&wqh_p, g_wqkvh);
        cudaGetSymbolAddress((void**)&wql_p, g_wqkvl);
        cudaGetSymbolAddress((void**)&wph_p, g_wph);
        cudaGetSymbolAddress((void**)&wpl_p, g_wpl);
    }

    // 0) Pre-split fp32 inputs into bf16 hi/lo
    split_pass<<<(M_ * C_ / 4 + 255) / 256, 256>>>(x, xh_p, xl_p, M_ * C_ / 4);
    split_pass<<<(C_ * 3 * C_ / 4 + 255) / 256, 256>>>(Wqkv, wqh_p, wql_p, C_ * 3 * C_ / 4);
    split_pass<<<(C_ * C_ / 4 + 255) / 256, 256>>>(Wproj, wph_p, wpl_p, C_ * C_ / 4);

    const int gemm_smem = 2 * (2 * 128 * 72 + 2 * 64 * 72) * (int)sizeof(__nv_bfloat16); // 110592

    // 1) QKV GEMM -> bf16 hi/lo Q,K,V
    {
        cudaFuncSetAttribute(gemm_pre<0>, cudaFuncAttributeMaxDynamicSharedMemorySize, gemm_smem);
        dim3 grid(3072 / 64, 8192 / 128);
        gemm_pre<0><<<grid, 256, gemm_smem>>>(bqkv, nullptr, M_, 3 * C_, C_);
    }

    // 2) Flash attention (2-stage KV pipeline), writes g_yh/g_yl
    {
        const int smem = (2 * 128 * 72 + 2 * 4 * 64 * 72) * (int)sizeof(__nv_bfloat16); // 110592
        cudaFuncSetAttribute(flash_mma_kernel, cudaFuncAttributeMaxDynamicSharedMemorySize, smem);
        flash_mma_kernel<<<dim3(16, 64), 256, smem>>>();
    }

    // 3) Projection GEMM: y @ Wproj + bproj -> out
    {
        cudaFuncSetAttribute(gemm_pre<1>, cudaFuncAttributeMaxDynamicSharedMemorySize, gemm_smem);
        dim3 grid(1024 / 64, 8192 / 128);
        gemm_pre<1><<<grid, 256, gemm_smem>>>(bproj, out, M_, C_, C_);
    }
}

// round 16
// speedup vs baseline: 1.3573x; 1.1761x over previous
#include <cuda_runtime.h>
#include <cuda_bf16.h>
#include <cuda_fp16.h>
#include <math.h>
#include <stdint.h>

// Problem constants
#define B_  4
#define T_  2048
#define C_  1024
#define NH_ 16
#define HD_ 64
#define BH_ (B_*NH_)     // 64
#define M_  (B_*T_)      // 8192

// Scratch (allocation-free device globals)
// GEMM operands: fp16, A-side split hi + scaled-lo (lo' = (x-hi)*2048, normal range)
__device__ __half g_xh[M_*C_],  g_xl[M_*C_];       // x split (lo scaled)
__device__ __half g_wqkvh[C_*3*C_];                // Wqkv hi [K][N]
__device__ __half g_wph[C_*C_];                    // Wproj hi [K][N]
__device__ __half g_yh[M_*C_],  g_yl[M_*C_];       // attention out split (lo scaled)
// Flash operands: bf16 hi/lo (unchanged bf16x3 numerics)
__device__ __nv_bfloat16 g_qh[BH_*T_*HD_], g_ql[BH_*T_*HD_];
__device__ __nv_bfloat16 g_kh[BH_*T_*HD_], g_kl[BH_*T_*HD_];
__device__ __nv_bfloat16 g_vh[BH_*T_*HD_], g_vl[BH_*T_*HD_];

__device__ __forceinline__ uint32_t smem_u32(const void* p) {
    return (uint32_t)__cvta_generic_to_shared(p);
}

#define LDSM4(R, ptr)                                                          \
    asm volatile("ldmatrix.sync.aligned.m8n8.x4.shared.b16 {%0,%1,%2,%3}, [%4];" \
                 : "=r"((R)[0]), "=r"((R)[1]), "=r"((R)[2]), "=r"((R)[3])      \
                 : "r"(smem_u32(ptr)))

#define LDSM4T(R, ptr)                                                         \
    asm volatile("ldmatrix.sync.aligned.m8n8.x4.trans.shared.b16 {%0,%1,%2,%3}, [%4];" \
                 : "=r"((R)[0]), "=r"((R)[1]), "=r"((R)[2]), "=r"((R)[3])      \
                 : "r"(smem_u32(ptr)))

// bf16 mma (flash)
#define MMA16816(D, A, b0, b1)                                                 \
    asm volatile("mma.sync.aligned.m16n8k16.row.col.f32.bf16.bf16.f32 "        \
                 "{%0,%1,%2,%3}, {%4,%5,%6,%7}, {%8,%9}, {%0,%1,%2,%3};"       \
                 : "+f"((D)[0]), "+f"((D)[1]), "+f"((D)[2]), "+f"((D)[3])      \
                 : "r"((A)[0]), "r"((A)[1]), "r"((A)[2]), "r"((A)[3]),         \
                   "r"(b0), "r"(b1))

// fp16 mma (GEMMs)
#define MMAF16(D, A, b0, b1)                                                   \
    asm volatile("mma.sync.aligned.m16n8k16.row.col.f32.f16.f16.f32 "          \
                 "{%0,%1,%2,%3}, {%4,%5,%6,%7}, {%8,%9}, {%0,%1,%2,%3};"       \
                 : "+f"((D)[0]), "+f"((D)[1]), "+f"((D)[2]), "+f"((D)[3])      \
                 : "r"((A)[0]), "r"((A)[1]), "r"((A)[2]), "r"((A)[3]),         \
                   "r"(b0), "r"(b1))

__device__ __forceinline__ void cp16(uint32_t dst, const void* src) {
    asm volatile("cp.async.cg.shared.global [%0], [%1], 16;" :: "r"(dst), "l"(src));
}
#define CP_COMMIT() asm volatile("cp.async.commit_group;")
#define CP_WAIT0()  asm volatile("cp.async.wait_group 0;")
#define CP_WAIT1()  asm volatile("cp.async.wait_group 1;")

__device__ __forceinline__ void split_bf16(float x, __nv_bfloat16& h, __nv_bfloat16& l) {
    h = __float2bfloat16(x);
    l = __float2bfloat16(x - __bfloat162float(h));
}

// fp16 hi + scaled lo (lo' = (x-h)*2048, exact scaling, normal range)
__device__ __forceinline__ void split_f16s(float x, __half& h, __half& l) {
    h = __float2half_rn(x);
    l = __float2half_rn((x - __half2float(h)) * 2048.0f);
}

__device__ __forceinline__ uint32_t pack2(float a, float b) {
    __nv_bfloat162 t = __halves2bfloat162(__float2bfloat16(a), __float2bfloat16(b));
    return *reinterpret_cast<uint32_t*>(&t);
}

// ---------------------------------------------------------------------------
// fp32 -> fp16 hi + scaled lo
// ---------------------------------------------------------------------------
__global__ __launch_bounds__(256) void split_f16_pass(
    const float* __restrict__ in, __half* __restrict__ oh,
    __half* __restrict__ ol, int n4)
{
    int i = blockIdx.x * blockDim.x + threadIdx.x;
    if (i >= n4) return;
    float4 v = reinterpret_cast<const float4*>(in)[i];
    __half h0, l0, h1, l1, h2, l2, h3, l3;
    split_f16s(v.x, h0, l0); split_f16s(v.y, h1, l1);
    split_f16s(v.z, h2, l2); split_f16s(v.w, h3, l3);
    reinterpret_cast<__half2*>(oh)[2*i]   = __halves2half2(h0, h1);
    reinterpret_cast<__half2*>(oh)[2*i+1] = __halves2half2(h2, h3);
    reinterpret_cast<__half2*>(ol)[2*i]   = __halves2half2(l0, l1);
    reinterpret_cast<__half2*>(ol)[2*i+1] = __halves2half2(l2, l3);
}

// fp32 -> fp16 hi only
__global__ __launch_bounds__(256) void conv_f16_pass(
    const float* __restrict__ in, __half* __restrict__ oh, int n4)
{
    int i = blockIdx.x * blockDim.x + threadIdx.x;
    if (i >= n4) return;
    float4 v = reinterpret_cast<const float4*>(in)[i];
    reinterpret_cast<__half2*>(oh)[2*i]   = __halves2half2(__float2half_rn(v.x), __float2half_rn(v.y));
    reinterpret_cast<__half2*>(oh)[2*i+1] = __halves2half2(__float2half_rn(v.z), __float2half_rn(v.w));
}

// ---------------------------------------------------------------------------
// GEMM, scaled-fp16 2-MMA: C = Ah*Wh + (Al'*Wh)/2048 + bias.
// cp.async 2-stage, BK=64, block 128x64, 8 warps (4m x 2n), warp tile 32x32.
// Separate fp32 accumulators for hi and lo products; combined in epilogue.
// MODE 0: A = g_x{h,l}, W = g_wqkvh; scatter bf16 hi/lo into q/k/v.
// MODE 1: A = g_y{h,l}, W = g_wph;  fp32 row-major output + bias.
// ---------------------------------------------------------------------------
template <int MODE>
__global__ __launch_bounds__(256, 2) void gemm_f16(
    const float* __restrict__ bias, float* __restrict__ Cout, int M, int N, int K)
{
    constexpr int LDA = 72;
    constexpr int LDB = 72;
    constexpr int ASZ = 128 * LDA;          // per A part
    constexpr int BSZ = 64 * LDB;           // B hi
    constexpr int STAGE = 2 * ASZ + BSZ;    // 23040 elems = 46080 B

    extern __shared__ __half smem[];

    const __half* Agh = (MODE == 0) ? g_xh : g_yh;
    const __half* Agl = (MODE == 0) ? g_xl : g_yl;
    const __half* Wgh = (MODE == 0) ? g_wqkvh : g_wph;

    int tid  = threadIdx.x;
    int lane = tid & 31, warp = tid >> 5;
    int cRow = blockIdx.y, cCol = blockIdx.x;
    int warpM = warp & 3, warpN = warp >> 2;
    int mr0 = warpM * 32;
    int n0w = warpN * 32;

    const __half* Abh = Agh + (size_t)cRow * 128 * K;
    const __half* Abl = Agl + (size_t)cRow * 128 * K;
    const __half* Wbh = Wgh + cCol * 64;

    uint32_t smem_base = smem_u32(smem);

    auto issue_stage = [&](int st, int k0) {
        uint32_t sb = smem_base + st * STAGE * 2;
        uint32_t ah = sb, al = sb + ASZ * 2, bh = sb + 2 * ASZ * 2;
        #pragma unroll
        for (int p = 0; p < 4; p++) {
            int id = tid + p * 256;
            int r = id >> 3, c8 = (id & 7) << 3;
            uint32_t so = (uint32_t)(r * LDA + c8) * 2;
            size_t go = (size_t)r * K + k0 + c8;
            cp16(ah + so, Abh + go);
            cp16(al + so, Abl + go);
        }
        #pragma unroll
        for (int p = 0; p < 2; p++) {
            int id = tid + p * 256;
            int r = id >> 3, c8 = (id & 7) << 3;
            cp16(bh + (uint32_t)(r * LDB + c8) * 2, Wbh + (size_t)(k0 + r) * N + c8);
        }
    };

    float acch[2][4][4], accl[2][4][4];
    #pragma unroll
    for (int i = 0; i < 2; i++)
        #pragma unroll
        for (int j = 0; j < 4; j++)
            #pragma unroll
            for (int q = 0; q < 4; q++) { acch[i][j][q] = 0.f; accl[i][j][q] = 0.f; }

    issue_stage(0, 0);
    CP_COMMIT();

    int NT = K / 64;
    for (int it = 0; it < NT; it++) {
        CP_WAIT0();
        __syncthreads();
        if (it + 1 < NT) {
            issue_stage((it + 1) & 1, (it + 1) * 64);
            CP_COMMIT();
        }

        __half* Ah = smem + (it & 1) * STAGE;
        __half* Al = Ah + ASZ;
        __half* Bh = Al + ASZ;

        #pragma unroll
        for (int ks = 0; ks < 4; ks++) {
            int kk = ks * 16;
            uint32_t ahf[2][4], alf[2][4], bhf[2][4];

            #pragma unroll
            for (int mi = 0; mi < 2; mi++) {
                int off = (mr0 + mi * 16 + (lane & 15)) * LDA + kk + ((lane >> 4) << 3);
                LDSM4(ahf[mi], &Ah[off]);
                LDSM4(alf[mi], &Al[off]);
            }
            #pragma unroll
            for (int g = 0; g < 2; g++) {
                int r = kk + ((lane & 16) >> 1) + (lane & 7);
                int c = n0w + g * 16 + (lane & 8);
                LDSM4T(bhf[g], &Bh[r * LDB + c]);
            }

            #pragma unroll
            for (int mi = 0; mi < 2; mi++)
                #pragma unroll
                for (int nj = 0; nj < 4; nj++) {
                    int g = nj >> 1, h = nj & 1;
                    uint32_t b0 = h ? bhf[g][1] : bhf[g][0];
                    uint32_t b1 = h ? bhf[g][3] : bhf[g][2];
                    MMAF16(acch[mi][nj], ahf[mi], b0, b1);
                    MMAF16(accl[mi][nj], alf[mi], b0, b1);
                }
        }
    }

    // --- epilogue: combine hi + lo/2048 ---
    const float inv2048 = 1.0f / 2048.0f;
    int rbase = cRow * 128 + mr0 + (lane >> 2);
    int cbase = cCol * 64 + n0w + ((lane & 3) << 1);

    #pragma unroll
    for (int mi = 0; mi < 2; mi++) {
        #pragma unroll
        for (int nj = 0; nj < 4; nj++) {
            int m0 = rbase + mi * 16;
            int n  = cbase + nj * 8;
            float bv0 = bias[n], bv1 = bias[n + 1];
            float v00 = fmaf(accl[mi][nj][0], inv2048, acch[mi][nj][0]) + bv0;
            float v01 = fmaf(accl[mi][nj][1], inv2048, acch[mi][nj][1]) + bv1;
            float v10 = fmaf(accl[mi][nj][2], inv2048, acch[mi][nj][2]) + bv0;
            float v11 = fmaf(accl[mi][nj][3], inv2048, acch[mi][nj][3]) + bv1;
            if (MODE == 1) {
                *reinterpret_cast<float2*>(&Cout[(size_t)m0 * N + n])       = make_float2(v00, v01);
                *reinterpret_cast<float2*>(&Cout[(size_t)(m0 + 8) * N + n]) = make_float2(v10, v11);
            } else {
                int which = n / C_;
                int c = n - which * C_;
                int h = c >> 6, d = c & 63;
                __nv_bfloat16* dh = (which == 0) ? g_qh : (which == 1) ? g_kh : g_vh;
                __nv_bfloat16* dl = (which == 0) ? g_ql : (which == 1) ? g_kl : g_vl;
                int b0i = m0 >> 11, t0 = m0 & 2047;
                int b1i = (m0 + 8) >> 11, t1 = (m0 + 8) & 2047;
                size_t i0 = (((size_t)b0i * NH_ + h) * T_ + t0) * HD_ + d;
                size_t i1 = (((size_t)b1i * NH_ + h) * T_ + t1) * HD_ + d;
                __nv_bfloat16 h00, l00, h01, l01, h10, l10, h11, l11;
                split_bf16(v00, h00, l00); split_bf16(v01, h01, l01);
                split_bf16(v10, h10, l10); split_bf16(v11, h11, l11);
                *reinterpret_cast<__nv_bfloat162*>(&dh[i0]) = __halves2bfloat162(h00, h01);
                *reinterpret_cast<__nv_bfloat162*>(&dl[i0]) = __halves2bfloat162(l00, l01);
                *reinterpret_cast<__nv_bfloat162*>(&dh[i1]) = __halves2bfloat162(h10, h11);
                *reinterpret_cast<__nv_bfloat162*>(&dl[i1]) = __halves2bfloat162(l10, l11);
            }
        }
    }
}

// ---------------------------------------------------------------------------
// Flash attention, bf16x3, causal. 2-stage cp.async K/V pipeline +
// diagonal warp skip. (R14, passing) Epilogue writes fp16 hi + scaled lo.
// ---------------------------------------------------------------------------
__global__ __launch_bounds__(256) void flash_mma_kernel()
{
    constexpr int LDS_ = 72;
    constexpr int KVPART = 64 * LDS_;
    constexpr int KVSTAGE = 4 * KVPART;
    extern __shared__ __nv_bfloat16 smf[];
    __nv_bfloat16* Qh  = smf;
    __nv_bfloat16* Ql  = Qh + 128 * LDS_;
    __nv_bfloat16* KV  = Ql + 128 * LDS_;

    int bh = blockIdx.y;
    int qt = gridDim.x - 1 - blockIdx.x;
    int q0 = qt * 128;
    int tid = threadIdx.x;
    int warp = tid >> 5, lane = tid & 31;
    int wrow = warp * 16;
    int g = lane >> 2, t2 = (lane & 3) << 1;

    const __nv_bfloat16* Qgh = g_qh + ((size_t)bh * T_ + q0) * HD_;
    const __nv_bfloat16* Qgl = g_ql + ((size_t)bh * T_ + q0) * HD_;

    #pragma unroll
    for (int i = 0; i < 4; i++) {
        int idx = (tid + i * 256) * 8;
        int r = idx >> 6, c = idx & 63;
        cp16(smem_u32(&Qh[r * LDS_ + c]), &Qgh[r * 64 + c]);
        cp16(smem_u32(&Ql[r * LDS_ + c]), &Qgl[r * 64 + c]);
    }
    CP_COMMIT();

    auto issue_kv = [&](int st, int k0) {
        __nv_bfloat16* Kh = KV + st * KVSTAGE;
        __nv_bfloat16* Kl = Kh + KVPART;
        __nv_bfloat16* Vh = Kl + KVPART;
        __nv_bfloat16* Vl = Vh + KVPART;
        const __nv_bfloat16* kgh = g_kh + ((size_t)bh * T_ + k0) * HD_;
        const __nv_bfloat16* kgl = g_kl + ((size_t)bh * T_ + k0) * HD_;
        const __nv_bfloat16* vgh = g_vh + ((size_t)bh * T_ + k0) * HD_;
        const __nv_bfloat16* vgl = g_vl + ((size_t)bh * T_ + k0) * HD_;
        #pragma unroll
        for (int i = 0; i < 2; i++) {
            int idx = (tid + i * 256) * 8;
            int r = idx >> 6, c = idx & 63;
            cp16(smem_u32(&Kh[r * LDS_ + c]), &kgh[r * 64 + c]);
            cp16(smem_u32(&Kl[r * LDS_ + c]), &kgl[r * 64 + c]);
            cp16(smem_u32(&Vh[r * LDS_ + c]), &vgh[r * 64 + c]);
            cp16(smem_u32(&Vl[r * LDS_ + c]), &vgl[r * 64 + c]);
        }
    };

    issue_kv(0, 0);
    CP_COMMIT();

    float O[8][4];
    #pragma unroll
    for (int i = 0; i < 8; i++)
        #pragma unroll
        for (int q = 0; q < 4; q++) O[i][q] = 0.f;
    float m0 = -INFINITY, m1 = -INFINITY, l0 = 0.f, l1 = 0.f;

    const float scale = 0.125f;
    int row0 = q0 + wrow + g;
    int row1 = row0 + 8;

    int kt_max = 2 * qt + 1;
    for (int kt = 0; kt <= kt_max; kt++) {
        int k0 = kt * 64;

        if (kt + 1 <= kt_max) {
            issue_kv((kt + 1) & 1, (kt + 1) * 64);
            CP_COMMIT();
            CP_WAIT1();
        } else {
            CP_WAIT0();
        }
        __syncthreads();

        __nv_bfloat16* Kh = KV + (kt & 1) * KVSTAGE;
        __nv_bfloat16* Kl = Kh + KVPART;
        __nv_bfloat16* Vh = Kl + KVPART;
        __nv_bfloat16* Vl = Vh + KVPART;

        bool active = !(kt == kt_max && wrow < 64);

        if (active) {
            float S[8][4];
            #pragma unroll
            for (int j = 0; j < 8; j++)
                #pragma unroll
                for (int q = 0; q < 4; q++) S[j][q] = 0.f;

            #pragma unroll
            for (int ks = 0; ks < 4; ks++) {
                int kk = ks * 16;
                uint32_t qhf[4], qlf[4];
                {
                    int off = (wrow + (lane & 15)) * LDS_ + kk + ((lane >> 4) << 3);
                    LDSM4(qhf, &Qh[off]);
                    LDSM4(qlf, &Ql[off]);
                }
                uint32_t bKh[8][2], bKl[8][2];
                #pragma unroll
                for (int tp = 0; tp < 4; tp++) {
                    uint32_t R[4];
                    int off = (tp * 16 + (lane & 7) + ((lane >> 4) << 3)) * LDS_
                              + kk + (((lane >> 3) & 1) << 3);
                    LDSM4(R, &Kh[off]);
                    bKh[2*tp][0] = R[0]; bKh[2*tp][1] = R[1];
                    bKh[2*tp+1][0] = R[2]; bKh[2*tp+1][1] = R[3];
                    LDSM4(R, &Kl[off]);
                    bKl[2*tp][0] = R[0]; bKl[2*tp][1] = R[1];
                    bKl[2*tp+1][0] = R[2]; bKl[2*tp+1][1] = R[3];
                }
                #pragma unroll
                for (int j = 0; j < 8; j++) {
                    MMA16816(S[j], qhf, bKh[j][0], bKh[j][1]);
                    MMA16816(S[j], qlf, bKh[j][0], bKh[j][1]);
                    MMA16816(S[j], qhf, bKl[j][0], bKl[j][1]);
                }
            }

            if (kt >= 2 * qt) {
                #pragma unroll
                for (int j = 0; j < 8; j++) {
                    int key = k0 + j * 8 + t2;
                    if (key     > row0) S[j][0] = -1e30f;
                    if (key + 1 > row0) S[j][1] = -1e30f;
                    if (key     > row1) S[j][2] = -1e30f;
                    if (key + 1 > row1) S[j][3] = -1e30f;
                }
            }

            float mx0 = -1e30f, mx1 = -1e30f;
            #pragma unroll
            for (int j = 0; j < 8; j++) {
                mx0 = fmaxf(mx0, fmaxf(S[j][0], S[j][1]));
                mx1 = fmaxf(mx1, fmaxf(S[j][2], S[j][3]));
            }
            #pragma unroll
            for (int off = 1; off <= 2; off <<= 1) {
                mx0 = fmaxf(mx0, __shfl_xor_sync(0xffffffffu, mx0, off));
                mx1 = fmaxf(mx1, __shfl_xor_sync(0xffffffffu, mx1, off));
            }
            float mn0 = fmaxf(m0, mx0 * scale);
            float mn1 = fmaxf(m1, mx1 * scale);
            float a0 = __expf(m0 - mn0);
            float a1 = __expf(m1 - mn1);
            m0 = mn0; m1 = mn1;

            float s0 = 0.f, s1 = 0.f;
            #pragma unroll
            for (int j = 0; j < 8; j++) {
                S[j][0] = __expf(fmaf(S[j][0], scale, -mn0));
                S[j][1] = __expf(fmaf(S[j][1], scale, -mn0));
                S[j][2] = __expf(fmaf(S[j][2], scale, -mn1));
                S[j][3] = __expf(fmaf(S[j][3], scale, -mn1));
                s0 += S[j][0] + S[j][1];
                s1 += S[j][2] + S[j][3];
            }
            #pragma unroll
            for (int off = 1; off <= 2; off <<= 1) {
                s0 += __shfl_xor_sync(0xffffffffu, s0, off);
                s1 += __shfl_xor_sync(0xffffffffu, s1, off);
            }
            l0 = l0 * a0 + s0;
            l1 = l1 * a1 + s1;
            #pragma unroll
            for (int i = 0; i < 8; i++) {
                O[i][0] *= a0; O[i][1] *= a0;
                O[i][2] *= a1; O[i][3] *= a1;
            }

            #pragma unroll
            for (int ks = 0; ks < 4; ks++) {
                int j0 = 2 * ks, j1 = 2 * ks + 1;
                uint32_t aPh[4], aPl[4];
                aPh[0] = pack2(S[j0][0], S[j0][1]);
                aPh[1] = pack2(S[j0][2], S[j0][3]);
                aPh[2] = pack2(S[j1][0], S[j1][1]);
                aPh[3] = pack2(S[j1][2], S[j1][3]);
                {
                    __nv_bfloat162 h;
                    h = *reinterpret_cast<__nv_bfloat162*>(&aPh[0]);
                    aPl[0] = pack2(S[j0][0] - __low2float(h), S[j0][1] - __high2float(h));
                    h = *reinterpret_cast<__nv_bfloat162*>(&aPh[1]);
                    aPl[1] = pack2(S[j0][2] - __low2float(h), S[j0][3] - __high2float(h));
                    h = *reinterpret_cast<__nv_bfloat162*>(&aPh[2]);
                    aPl[2] = pack2(S[j1][0] - __low2float(h), S[j1][1] - __high2float(h));
                    h = *reinterpret_cast<__nv_bfloat162*>(&aPh[3]);
                    aPl[3] = pack2(S[j1][2] - __low2float(h), S[j1][3] - __high2float(h));
                }
                uint32_t Rh[4][4], Rl[4][4];
                #pragma unroll
                for (int gd = 0; gd < 4; gd++) {
                    int off = (ks * 16 + ((lane & 16) >> 1) + (lane & 7)) * LDS_
                              + gd * 16 + (lane & 8);
                    LDSM4T(Rh[gd], &Vh[off]);
                    LDSM4T(Rl[gd], &Vl[off]);
                }
                #pragma unroll
                for (int gd = 0; gd < 4; gd++) {
                    MMA16816(O[gd*2+0], aPh, Rh[gd][0], Rh[gd][2]);
                    MMA16816(O[gd*2+1], aPh, Rh[gd][1], Rh[gd][3]);
                    MMA16816(O[gd*2+0], aPl, Rh[gd][0], Rh[gd][2]);
                    MMA16816(O[gd*2+1], aPl, Rh[gd][1], Rh[gd][3]);
                    MMA16816(O[gd*2+0], aPh, Rl[gd][0], Rl[gd][2]);
                    MMA16816(O[gd*2+1], aPh, Rl[gd][1], Rl[gd][3]);
                }
            }
        }
        __syncthreads();
    }

    // epilogue: write y as fp16 hi + scaled lo (for scaled-fp16 proj GEMM)
    int b = bh >> 4, h = bh & 15;
    float inv0 = 1.f / l0, inv1 = 1.f / l1;
    size_t base0 = ((size_t)b * T_ + row0) * C_ + h * 64 + t2;
    size_t base1 = ((size_t)b * T_ + row1) * C_ + h * 64 + t2;
    #pragma unroll
    for (int i = 0; i < 8; i++) {
        float v0 = O[i][0] * inv0, v1 = O[i][1] * inv0;
        float v2 = O[i][2] * inv1, v3 = O[i][3] * inv1;
        __half h0, l0b, h1, l1b, h2, l2b, h3, l3b;
        split_f16s(v0, h0, l0b); split_f16s(v1, h1, l1b);
        split_f16s(v2, h2, l2b); split_f16s(v3, h3, l3b);
        *reinterpret_cast<__half2*>(&g_yh[base0 + i * 8]) = __halves2half2(h0, h1);
        *reinterpret_cast<__half2*>(&g_yl[base0 + i * 8]) = __halves2half2(l0b, l1b);
        *reinterpret_cast<__half2*>(&g_yh[base1 + i * 8]) = __halves2half2(h2, h3);
        *reinterpret_cast<__half2*>(&g_yl[base1 + i * 8]) = __halves2half2(l2b, l3b);
    }
}

// ---------------------------------------------------------------------------
extern "C" void kernel_launch(void* const* d_in, const int* in_sizes, int n_in,
                              void* d_out, int out_size)
{
    const float* x     = (const float*)d_in[0];
    const float* Wqkv  = (const float*)d_in[1];
    const float* bqkv  = (const float*)d_in[2];
    const float* Wproj = (const float*)d_in[3];
    const float* bproj = (const float*)d_in[4];
    float* out = (float*)d_out;

    static __half *xh_p = nullptr, *xl_p, *wqh_p, *wph_p;
    if (!xh_p) {
        cudaGetSymbolAddress((void**)&xh_p,  g_xh);
        cudaGetSymbolAddress((void**)&xl_p,  g_xl);
        cudaGetSymbolAddress((void**)&wqh_p, g_wqkvh);
        cudaGetSymbolAddress((void**)&wph_p, g_wph);
    }

    // 0) Pre-split x (fp16 hi + scaled lo); convert weights (fp16 hi)
    split_f16_pass<<<(M_ * C_ / 4 + 255) / 256, 256>>>(x, xh_p, xl_p, M_ * C_ / 4);
    conv_f16_pass<<<(C_ * 3 * C_ / 4 + 255) / 256, 256>>>(Wqkv, wqh_p, C_ * 3 * C_ / 4);
    conv_f16_pass<<<(C_ * C_ / 4 + 255) / 256, 256>>>(Wproj, wph_p, C_ * C_ / 4);

    const int gemm_smem = 2 * (2 * 128 * 72 + 64 * 72) * (int)sizeof(__half); // 92160

    // 1) QKV GEMM (scaled-fp16 2-MMA) -> bf16 hi/lo Q,K,V
    {
        cudaFuncSetAttribute(gemm_f16<0>, cudaFuncAttributeMaxDynamicSharedMemorySize, gemm_smem);
        dim3 grid(3072 / 64, 8192 / 128);
        gemm_f16<0><<<grid, 256, gemm_smem>>>(bqkv, nullptr, M_, 3 * C_, C_);
    }

    // 2) Flash attention (bf16x3, 2-stage KV pipeline), writes g_yh/g_yl (fp16)
    {
        const int smem = (2 * 128 * 72 + 2 * 4 * 64 * 72) * (int)sizeof(__nv_bfloat16); // 110592
        cudaFuncSetAttribute(flash_mma_kernel, cudaFuncAttributeMaxDynamicSharedMemorySize, smem);
        flash_mma_kernel<<<dim3(16, 64), 256, smem>>>();
    }

    // 3) Projection GEMM (scaled-fp16 2-MMA): y @ Wproj + bproj -> out
    {
        cudaFuncSetAttribute(gemm_f16<1>, cudaFuncAttributeMaxDynamicSharedMemorySize, gemm_smem);
        dim3 grid(1024 / 64, 8192 / 128);
        gemm_f16<1><<<grid, 256, gemm_smem>>>(bproj, out, M_, C_, C_);
    }
}

// round 17
// speedup vs baseline: 1.6604x; 1.2233x over previous
#include <cuda_runtime.h>
#include <cuda_fp16.h>
#include <math.h>
#include <stdint.h>

// Problem constants
#define B_  4
#define T_  2048
#define C_  1024
#define NH_ 16
#define HD_ 64
#define BH_ (B_*NH_)     // 64
#define M_  (B_*T_)      // 8192

// Scratch (allocation-free device globals), all fp16.
// A-side operands split as hi + scaled-lo (lo' = (x-hi)*2048, exact, normal range).
__device__ __half g_xh[M_*C_],  g_xl[M_*C_];       // x split
__device__ __half g_wqkvh[C_*3*C_];                // Wqkv hi [K][N]
__device__ __half g_wph[C_*C_];                    // Wproj hi [K][N]
__device__ __half g_qh[BH_*T_*HD_], g_ql[BH_*T_*HD_];  // Q hi + scaled lo
__device__ __half g_kh[BH_*T_*HD_];                // K hi only
__device__ __half g_vh[BH_*T_*HD_];                // V hi only
__device__ __half g_yh[M_*C_],  g_yl[M_*C_];       // attention out split

__device__ __forceinline__ uint32_t smem_u32(const void* p) {
    return (uint32_t)__cvta_generic_to_shared(p);
}

#define LDSM4(R, ptr)                                                          \
    asm volatile("ldmatrix.sync.aligned.m8n8.x4.shared.b16 {%0,%1,%2,%3}, [%4];" \
                 : "=r"((R)[0]), "=r"((R)[1]), "=r"((R)[2]), "=r"((R)[3])      \
                 : "r"(smem_u32(ptr)))

#define LDSM4T(R, ptr)                                                         \
    asm volatile("ldmatrix.sync.aligned.m8n8.x4.trans.shared.b16 {%0,%1,%2,%3}, [%4];" \
                 : "=r"((R)[0]), "=r"((R)[1]), "=r"((R)[2]), "=r"((R)[3])      \
                 : "r"(smem_u32(ptr)))

#define MMAF16(D, A, b0, b1)                                                   \
    asm volatile("mma.sync.aligned.m16n8k16.row.col.f32.f16.f16.f32 "          \
                 "{%0,%1,%2,%3}, {%4,%5,%6,%7}, {%8,%9}, {%0,%1,%2,%3};"       \
                 : "+f"((D)[0]), "+f"((D)[1]), "+f"((D)[2]), "+f"((D)[3])      \
                 : "r"((A)[0]), "r"((A)[1]), "r"((A)[2]), "r"((A)[3]),         \
                   "r"(b0), "r"(b1))

__device__ __forceinline__ void cp16(uint32_t dst, const void* src) {
    asm volatile("cp.async.cg.shared.global [%0], [%1], 16;" :: "r"(dst), "l"(src));
}
#define CP_COMMIT() asm volatile("cp.async.commit_group;")
#define CP_WAIT0()  asm volatile("cp.async.wait_group 0;")
#define CP_WAIT1()  asm volatile("cp.async.wait_group 1;")

// fp16 hi + scaled lo (lo' = (x-h)*2048)
__device__ __forceinline__ void split_f16s(float x, __half& h, __half& l) {
    h = __float2half_rn(x);
    l = __float2half_rn((x - __half2float(h)) * 2048.0f);
}

__device__ __forceinline__ uint32_t pack2h(float a, float b) {
    __half2 t = __halves2half2(__float2half_rn(a), __float2half_rn(b));
    return *reinterpret_cast<uint32_t*>(&t);
}

// ---------------------------------------------------------------------------
// fp32 -> fp16 hi + scaled lo
// ---------------------------------------------------------------------------
__global__ __launch_bounds__(256) void split_f16_pass(
    const float* __restrict__ in, __half* __restrict__ oh,
    __half* __restrict__ ol, int n4)
{
    int i = blockIdx.x * blockDim.x + threadIdx.x;
    if (i >= n4) return;
    float4 v = reinterpret_cast<const float4*>(in)[i];
    __half h0, l0, h1, l1, h2, l2, h3, l3;
    split_f16s(v.x, h0, l0); split_f16s(v.y, h1, l1);
    split_f16s(v.z, h2, l2); split_f16s(v.w, h3, l3);
    reinterpret_cast<__half2*>(oh)[2*i]   = __halves2half2(h0, h1);
    reinterpret_cast<__half2*>(oh)[2*i+1] = __halves2half2(h2, h3);
    reinterpret_cast<__half2*>(ol)[2*i]   = __halves2half2(l0, l1);
    reinterpret_cast<__half2*>(ol)[2*i+1] = __halves2half2(l2, l3);
}

// fp32 -> fp16 hi only
__global__ __launch_bounds__(256) void conv_f16_pass(
    const float* __restrict__ in, __half* __restrict__ oh, int n4)
{
    int i = blockIdx.x * blockDim.x + threadIdx.x;
    if (i >= n4) return;
    float4 v = reinterpret_cast<const float4*>(in)[i];
    reinterpret_cast<__half2*>(oh)[2*i]   = __halves2half2(__float2half_rn(v.x), __float2half_rn(v.y));
    reinterpret_cast<__half2*>(oh)[2*i+1] = __halves2half2(__float2half_rn(v.z), __float2half_rn(v.w));
}

// ---------------------------------------------------------------------------
// GEMM, scaled-fp16 2-MMA: C = Ah*Wh + (Al'*Wh)/2048 + bias. (R16, passing)
// MODE 0: scatter q (hi + scaled lo), k (hi), v (hi).
// MODE 1: fp32 row-major output + bias.
// ---------------------------------------------------------------------------
template <int MODE>
__global__ __launch_bounds__(256, 2) void gemm_f16(
    const float* __restrict__ bias, float* __restrict__ Cout, int M, int N, int K)
{
    constexpr int LDA = 72;
    constexpr int LDB = 72;
    constexpr int ASZ = 128 * LDA;
    constexpr int BSZ = 64 * LDB;
    constexpr int STAGE = 2 * ASZ + BSZ;

    extern __shared__ __half smem[];

    const __half* Agh = (MODE == 0) ? g_xh : g_yh;
    const __half* Agl = (MODE == 0) ? g_xl : g_yl;
    const __half* Wgh = (MODE == 0) ? g_wqkvh : g_wph;

    int tid  = threadIdx.x;
    int lane = tid & 31, warp = tid >> 5;
    int cRow = blockIdx.y, cCol = blockIdx.x;
    int warpM = warp & 3, warpN = warp >> 2;
    int mr0 = warpM * 32;
    int n0w = warpN * 32;

    const __half* Abh = Agh + (size_t)cRow * 128 * K;
    const __half* Abl = Agl + (size_t)cRow * 128 * K;
    const __half* Wbh = Wgh + cCol * 64;

    uint32_t smem_base = smem_u32(smem);

    auto issue_stage = [&](int st, int k0) {
        uint32_t sb = smem_base + st * STAGE * 2;
        uint32_t ah = sb, al = sb + ASZ * 2, bh = sb + 2 * ASZ * 2;
        #pragma unroll
        for (int p = 0; p < 4; p++) {
            int id = tid + p * 256;
            int r = id >> 3, c8 = (id & 7) << 3;
            uint32_t so = (uint32_t)(r * LDA + c8) * 2;
            size_t go = (size_t)r * K + k0 + c8;
            cp16(ah + so, Abh + go);
            cp16(al + so, Abl + go);
        }
        #pragma unroll
        for (int p = 0; p < 2; p++) {
            int id = tid + p * 256;
            int r = id >> 3, c8 = (id & 7) << 3;
            cp16(bh + (uint32_t)(r * LDB + c8) * 2, Wbh + (size_t)(k0 + r) * N + c8);
        }
    };

    float acch[2][4][4], accl[2][4][4];
    #pragma unroll
    for (int i = 0; i < 2; i++)
        #pragma unroll
        for (int j = 0; j < 4; j++)
            #pragma unroll
            for (int q = 0; q < 4; q++) { acch[i][j][q] = 0.f; accl[i][j][q] = 0.f; }

    issue_stage(0, 0);
    CP_COMMIT();

    int NT = K / 64;
    for (int it = 0; it < NT; it++) {
        CP_WAIT0();
        __syncthreads();
        if (it + 1 < NT) {
            issue_stage((it + 1) & 1, (it + 1) * 64);
            CP_COMMIT();
        }

        __half* Ah = smem + (it & 1) * STAGE;
        __half* Al = Ah + ASZ;
        __half* Bh = Al + ASZ;

        #pragma unroll
        for (int ks = 0; ks < 4; ks++) {
            int kk = ks * 16;
            uint32_t ahf[2][4], alf[2][4], bhf[2][4];

            #pragma unroll
            for (int mi = 0; mi < 2; mi++) {
                int off = (mr0 + mi * 16 + (lane & 15)) * LDA + kk + ((lane >> 4) << 3);
                LDSM4(ahf[mi], &Ah[off]);
                LDSM4(alf[mi], &Al[off]);
            }
            #pragma unroll
            for (int g = 0; g < 2; g++) {
                int r = kk + ((lane & 16) >> 1) + (lane & 7);
                int c = n0w + g * 16 + (lane & 8);
                LDSM4T(bhf[g], &Bh[r * LDB + c]);
            }

            #pragma unroll
            for (int mi = 0; mi < 2; mi++)
                #pragma unroll
                for (int nj = 0; nj < 4; nj++) {
                    int g = nj >> 1, h = nj & 1;
                    uint32_t b0 = h ? bhf[g][1] : bhf[g][0];
                    uint32_t b1 = h ? bhf[g][3] : bhf[g][2];
                    MMAF16(acch[mi][nj], ahf[mi], b0, b1);
                    MMAF16(accl[mi][nj], alf[mi], b0, b1);
                }
        }
    }

    // --- epilogue: combine hi + lo/2048 ---
    const float inv2048 = 1.0f / 2048.0f;
    int rbase = cRow * 128 + mr0 + (lane >> 2);
    int cbase = cCol * 64 + n0w + ((lane & 3) << 1);

    #pragma unroll
    for (int mi = 0; mi < 2; mi++) {
        #pragma unroll
        for (int nj = 0; nj < 4; nj++) {
            int m0 = rbase + mi * 16;
            int n  = cbase + nj * 8;
            float bv0 = bias[n], bv1 = bias[n + 1];
            float v00 = fmaf(accl[mi][nj][0], inv2048, acch[mi][nj][0]) + bv0;
            float v01 = fmaf(accl[mi][nj][1], inv2048, acch[mi][nj][1]) + bv1;
            float v10 = fmaf(accl[mi][nj][2], inv2048, acch[mi][nj][2]) + bv0;
            float v11 = fmaf(accl[mi][nj][3], inv2048, acch[mi][nj][3]) + bv1;
            if (MODE == 1) {
                *reinterpret_cast<float2*>(&Cout[(size_t)m0 * N + n])       = make_float2(v00, v01);
                *reinterpret_cast<float2*>(&Cout[(size_t)(m0 + 8) * N + n]) = make_float2(v10, v11);
            } else {
                int which = n / C_;
                int c = n - which * C_;
                int h = c >> 6, d = c & 63;
                int b0i = m0 >> 11, t0 = m0 & 2047;
                int b1i = (m0 + 8) >> 11, t1 = (m0 + 8) & 2047;
                size_t i0 = (((size_t)b0i * NH_ + h) * T_ + t0) * HD_ + d;
                size_t i1 = (((size_t)b1i * NH_ + h) * T_ + t1) * HD_ + d;
                if (which == 0) {
                    __half h00, l00, h01, l01, h10, l10, h11, l11;
                    split_f16s(v00, h00, l00); split_f16s(v01, h01, l01);
                    split_f16s(v10, h10, l10); split_f16s(v11, h11, l11);
                    *reinterpret_cast<__half2*>(&g_qh[i0]) = __halves2half2(h00, h01);
                    *reinterpret_cast<__half2*>(&g_ql[i0]) = __halves2half2(l00, l01);
                    *reinterpret_cast<__half2*>(&g_qh[i1]) = __halves2half2(h10, h11);
                    *reinterpret_cast<__half2*>(&g_ql[i1]) = __halves2half2(l10, l11);
                } else {
                    __half* dh = (which == 1) ? g_kh : g_vh;
                    *reinterpret_cast<__half2*>(&dh[i0]) =
                        __halves2half2(__float2half_rn(v00), __float2half_rn(v01));
                    *reinterpret_cast<__half2*>(&dh[i1]) =
                        __halves2half2(__float2half_rn(v10), __float2half_rn(v11));
                }
            }
        }
    }
}

// ---------------------------------------------------------------------------
// Flash attention, scaled-fp16, causal.
// S = Qh*Kh + (Ql'*Kh)/2048 (Sl folded per k16 step); PV = P(fp16)*Vh.
// 2-stage cp.async K/V pipeline + diagonal warp skip.
// smem: Qh,Ql [128][72] + 2 stages x (Kh,Vh)[64][72] = 73728 B.
// ---------------------------------------------------------------------------
__global__ __launch_bounds__(256) void flash_mma_kernel()
{
    constexpr int LDS_ = 72;
    constexpr int KVPART = 64 * LDS_;
    constexpr int KVSTAGE = 2 * KVPART;       // Kh, Vh per stage
    extern __shared__ __half smf[];
    __half* Qh  = smf;                        // [128][72]
    __half* Ql  = Qh + 128 * LDS_;
    __half* KV  = Ql + 128 * LDS_;            // 2 stages

    int bh = blockIdx.y;
    int qt = gridDim.x - 1 - blockIdx.x;
    int q0 = qt * 128;
    int tid = threadIdx.x;
    int warp = tid >> 5, lane = tid & 31;
    int wrow = warp * 16;
    int g = lane >> 2, t2 = (lane & 3) << 1;

    const __half* Qgh = g_qh + ((size_t)bh * T_ + q0) * HD_;
    const __half* Qgl = g_ql + ((size_t)bh * T_ + q0) * HD_;

    #pragma unroll
    for (int i = 0; i < 4; i++) {
        int idx = (tid + i * 256) * 8;
        int r = idx >> 6, c = idx & 63;
        cp16(smem_u32(&Qh[r * LDS_ + c]), &Qgh[r * 64 + c]);
        cp16(smem_u32(&Ql[r * LDS_ + c]), &Qgl[r * 64 + c]);
    }
    CP_COMMIT();

    auto issue_kv = [&](int st, int k0) {
        __half* Kh = KV + st * KVSTAGE;
        __half* Vh = Kh + KVPART;
        const __half* kgh = g_kh + ((size_t)bh * T_ + k0) * HD_;
        const __half* vgh = g_vh + ((size_t)bh * T_ + k0) * HD_;
        #pragma unroll
        for (int i = 0; i < 2; i++) {
            int idx = (tid + i * 256) * 8;
            int r = idx >> 6, c = idx & 63;
            cp16(smem_u32(&Kh[r * LDS_ + c]), &kgh[r * 64 + c]);
            cp16(smem_u32(&Vh[r * LDS_ + c]), &vgh[r * 64 + c]);
        }
    };

    issue_kv(0, 0);
    CP_COMMIT();

    float O[8][4];
    #pragma unroll
    for (int i = 0; i < 8; i++)
        #pragma unroll
        for (int q = 0; q < 4; q++) O[i][q] = 0.f;
    float m0 = -INFINITY, m1 = -INFINITY, l0 = 0.f, l1 = 0.f;

    const float scale = 0.125f;
    const float inv2048 = 1.0f / 2048.0f;
    int row0 = q0 + wrow + g;
    int row1 = row0 + 8;

    int kt_max = 2 * qt + 1;
    for (int kt = 0; kt <= kt_max; kt++) {
        int k0 = kt * 64;

        if (kt + 1 <= kt_max) {
            issue_kv((kt + 1) & 1, (kt + 1) * 64);
            CP_COMMIT();
            CP_WAIT1();
        } else {
            CP_WAIT0();
        }
        __syncthreads();

        __half* Kh = KV + (kt & 1) * KVSTAGE;
        __half* Vh = Kh + KVPART;

        bool active = !(kt == kt_max && wrow < 64);

        if (active) {
            float S[8][4];
            #pragma unroll
            for (int j = 0; j < 8; j++)
                #pragma unroll
                for (int q = 0; q < 4; q++) S[j][q] = 0.f;

            #pragma unroll
            for (int ks = 0; ks < 4; ks++) {
                int kk = ks * 16;
                uint32_t qhf[4], qlf[4];
                {
                    int off = (wrow + (lane & 15)) * LDS_ + kk + ((lane >> 4) << 3);
                    LDSM4(qhf, &Qh[off]);
                    LDSM4(qlf, &Ql[off]);
                }
                uint32_t bKh[8][2];
                #pragma unroll
                for (int tp = 0; tp < 4; tp++) {
                    uint32_t R[4];
                    int off = (tp * 16 + (lane & 7) + ((lane >> 4) << 3)) * LDS_
                              + kk + (((lane >> 3) & 1) << 3);
                    LDSM4(R, &Kh[off]);
                    bKh[2*tp][0] = R[0]; bKh[2*tp][1] = R[1];
                    bKh[2*tp+1][0] = R[2]; bKh[2*tp+1][1] = R[3];
                }
                // hi product into S
                #pragma unroll
                for (int j = 0; j < 8; j++)
                    MMAF16(S[j], qhf, bKh[j][0], bKh[j][1]);
                // scaled-lo product into transient Sl, folded immediately
                float Sl[8][4];
                #pragma unroll
                for (int j = 0; j < 8; j++)
                    #pragma unroll
                    for (int q = 0; q < 4; q++) Sl[j][q] = 0.f;
                #pragma unroll
                for (int j = 0; j < 8; j++)
                    MMAF16(Sl[j], qlf, bKh[j][0], bKh[j][1]);
                #pragma unroll
                for (int j = 0; j < 8; j++)
                    #pragma unroll
                    for (int q = 0; q < 4; q++)
                        S[j][q] = fmaf(Sl[j][q], inv2048, S[j][q]);
            }

            if (kt >= 2 * qt) {
                #pragma unroll
                for (int j = 0; j < 8; j++) {
                    int key = k0 + j * 8 + t2;
                    if (key     > row0) S[j][0] = -1e30f;
                    if (key + 1 > row0) S[j][1] = -1e30f;
                    if (key     > row1) S[j][2] = -1e30f;
                    if (key + 1 > row1) S[j][3] = -1e30f;
                }
            }

            float mx0 = -1e30f, mx1 = -1e30f;
            #pragma unroll
            for (int j = 0; j < 8; j++) {
                mx0 = fmaxf(mx0, fmaxf(S[j][0], S[j][1]));
                mx1 = fmaxf(mx1, fmaxf(S[j][2], S[j][3]));
            }
            #pragma unroll
            for (int off = 1; off <= 2; off <<= 1) {
                mx0 = fmaxf(mx0, __shfl_xor_sync(0xffffffffu, mx0, off));
                mx1 = fmaxf(mx1, __shfl_xor_sync(0xffffffffu, mx1, off));
            }
            float mn0 = fmaxf(m0, mx0 * scale);
            float mn1 = fmaxf(m1, mx1 * scale);
            float a0 = __expf(m0 - mn0);
            float a1 = __expf(m1 - mn1);
            m0 = mn0; m1 = mn1;

            float s0 = 0.f, s1 = 0.f;
            #pragma unroll
            for (int j = 0; j < 8; j++) {
                S[j][0] = __expf(fmaf(S[j][0], scale, -mn0));
                S[j][1] = __expf(fmaf(S[j][1], scale, -mn0));
                S[j][2] = __expf(fmaf(S[j][2], scale, -mn1));
                S[j][3] = __expf(fmaf(S[j][3], scale, -mn1));
                s0 += S[j][0] + S[j][1];
                s1 += S[j][2] + S[j][3];
            }
            #pragma unroll
            for (int off = 1; off <= 2; off <<= 1) {
                s0 += __shfl_xor_sync(0xffffffffu, s0, off);
                s1 += __shfl_xor_sync(0xffffffffu, s1, off);
            }
            l0 = l0 * a0 + s0;
            l1 = l1 * a1 + s1;
            #pragma unroll
            for (int i = 0; i < 8; i++) {
                O[i][0] *= a0; O[i][1] *= a0;
                O[i][2] *= a1; O[i][3] *= a1;
            }

            // ---- O += P Vh, single fp16 MMA per fragment ----
            #pragma unroll
            for (int ks = 0; ks < 4; ks++) {
                int j0 = 2 * ks, j1 = 2 * ks + 1;
                uint32_t aP[4];
                aP[0] = pack2h(S[j0][0], S[j0][1]);
                aP[1] = pack2h(S[j0][2], S[j0][3]);
                aP[2] = pack2h(S[j1][0], S[j1][1]);
                aP[3] = pack2h(S[j1][2], S[j1][3]);
                uint32_t Rh[4][4];
                #pragma unroll
                for (int gd = 0; gd < 4; gd++) {
                    int off = (ks * 16 + ((lane & 16) >> 1) + (lane & 7)) * LDS_
                              + gd * 16 + (lane & 8);
                    LDSM4T(Rh[gd], &Vh[off]);
                }
                #pragma unroll
                for (int gd = 0; gd < 4; gd++) {
                    MMAF16(O[gd*2+0], aP, Rh[gd][0], Rh[gd][2]);
                    MMAF16(O[gd*2+1], aP, Rh[gd][1], Rh[gd][3]);
                }
            }
        }
        __syncthreads();
    }

    // epilogue: write y as fp16 hi + scaled lo
    int b = bh >> 4, h = bh & 15;
    float inv0 = 1.f / l0, inv1 = 1.f / l1;
    size_t base0 = ((size_t)b * T_ + row0) * C_ + h * 64 + t2;
    size_t base1 = ((size_t)b * T_ + row1) * C_ + h * 64 + t2;
    #pragma unroll
    for (int i = 0; i < 8; i++) {
        float v0 = O[i][0] * inv0, v1 = O[i][1] * inv0;
        float v2 = O[i][2] * inv1, v3 = O[i][3] * inv1;
        __half h0, l0b, h1, l1b, h2, l2b, h3, l3b;
        split_f16s(v0, h0, l0b); split_f16s(v1, h1, l1b);
        split_f16s(v2, h2, l2b); split_f16s(v3, h3, l3b);
        *reinterpret_cast<__half2*>(&g_yh[base0 + i * 8]) = __halves2half2(h0, h1);
        *reinterpret_cast<__half2*>(&g_yl[base0 + i * 8]) = __halves2half2(l0b, l1b);
        *reinterpret_cast<__half2*>(&g_yh[base1 + i * 8]) = __halves2half2(h2, h3);
        *reinterpret_cast<__half2*>(&g_yl[base1 + i * 8]) = __halves2half2(l2b, l3b);
    }
}

// ---------------------------------------------------------------------------
extern "C" void kernel_launch(void* const* d_in, const int* in_sizes, int n_in,
                              void* d_out, int out_size)
{
    const float* x     = (const float*)d_in[0];
    const float* Wqkv  = (const float*)d_in[1];
    const float* bqkv  = (const float*)d_in[2];
    const float* Wproj = (const float*)d_in[3];
    const float* bproj = (const float*)d_in[4];
    float* out = (float*)d_out;

    static __half *xh_p = nullptr, *xl_p, *wqh_p, *wph_p;
    if (!xh_p) {
        cudaGetSymbolAddress((void**)&xh_p,  g_xh);
        cudaGetSymbolAddress((void**)&xl_p,  g_xl);
        cudaGetSymbolAddress((void**)&wqh_p, g_wqkvh);
        cudaGetSymbolAddress((void**)&wph_p, g_wph);
    }

    // 0) Pre-split x (fp16 hi + scaled lo); convert weights (fp16 hi)
    split_f16_pass<<<(M_ * C_ / 4 + 255) / 256, 256>>>(x, xh_p, xl_p, M_ * C_ / 4);
    conv_f16_pass<<<(C_ * 3 * C_ / 4 + 255) / 256, 256>>>(Wqkv, wqh_p, C_ * 3 * C_ / 4);
    conv_f16_pass<<<(C_ * C_ / 4 + 255) / 256, 256>>>(Wproj, wph_p, C_ * C_ / 4);

    const int gemm_smem = 2 * (2 * 128 * 72 + 64 * 72) * (int)sizeof(__half); // 92160

    // 1) QKV GEMM (scaled-fp16 2-MMA) -> q(hi,lo'), k(hi), v(hi)
    {
        cudaFuncSetAttribute(gemm_f16<0>, cudaFuncAttributeMaxDynamicSharedMemorySize, gemm_smem);
        dim3 grid(3072 / 64, 8192 / 128);
        gemm_f16<0><<<grid, 256, gemm_smem>>>(bqkv, nullptr, M_, 3 * C_, C_);
    }

    // 2) Flash attention (scaled-fp16, 2-stage KV pipeline), writes g_yh/g_yl
    {
        const int smem = (2 * 128 * 72 + 2 * 2 * 64 * 72) * (int)sizeof(__half); // 73728
        cudaFuncSetAttribute(flash_mma_kernel, cudaFuncAttributeMaxDynamicSharedMemorySize, smem);
        flash_mma_kernel<<<dim3(16, 64), 256, smem>>>();
    }

    // 3) Projection GEMM (scaled-fp16 2-MMA): y @ Wproj + bproj -> out
    {
        cudaFuncSetAttribute(gemm_f16<1>, cudaFuncAttributeMaxDynamicSharedMemorySize, gemm_smem);
        dim3 grid(1024 / 64, 8192 / 128);
        gemm_f16<1><<<grid, 256, gemm_smem>>>(bproj, out, M_, C_, C_);
    }
}